// round 3
// baseline (speedup 1.0000x reference)
#include <cuda_runtime.h>
#include <cuda_bf16.h>

// Problem constants (from reference)
#define N_NODES  100000
#define N_EDGES  500000
#define IN_FEATS 256
#define HIDDEN   64

// Scratch: per-node partial MLP activations.
//   g_A[n][j] = h[n] @ W1[0:256, j]   + b1[j]
//   g_B[n][j] = h[n] @ W1[256:512, j]
__device__ float g_A[(size_t)N_NODES * HIDDEN];
__device__ float g_B[(size_t)N_NODES * HIDDEN];

// ---------------------------------------------------------------------------
// Kernel 1: node GEMM.  C[100000, 128] = h[100000, 256] @ Wcat[256, 128]
// where Wcat[k, j] = W1[k, j] for j<64 and W1[256+k, j-64] for j>=64.
// Tile: 64 rows per block, 256 threads. Entire Wcat (128 KB) staged in smem,
// plus the 64-row h tile (64 KB). 192 KB dynamic smem -> 1 CTA/SM, 8 warps.
// Thread (rg, j): rg = tid>>7 owns rows rg*32..rg*32+31, j = tid&127 owns col.
// ---------------------------------------------------------------------------
__global__ __launch_bounds__(256, 1)
void node_gemm_kernel(const float* __restrict__ h,
                      const float* __restrict__ W1,
                      const float* __restrict__ b1,
                      int n_nodes)
{
    extern __shared__ float smem[];
    float*  Wsh = smem;                         // [256][128] = 32768 floats (128 KB)
    float4* hs4 = (float4*)(smem + 32768);      // [64 rows][64 float4]      (64 KB)

    const int tid = threadIdx.x;
    const int node0 = blockIdx.x * 64;

    // Stage Wcat into shared: Wsh[k*128 + j]
    #pragma unroll 4
    for (int i = tid; i < 256 * 128; i += 256) {
        int k = i >> 7;
        int j = i & 127;
        float w = (j < 64) ? W1[k * 64 + j] : W1[(256 + k) * 64 + (j - 64)];
        Wsh[i] = w;
    }

    // Stage 64-row h tile (each row: 256 floats = 64 float4), guarded.
    #pragma unroll 4
    for (int i = tid; i < 64 * 64; i += 256) {
        int r  = i >> 6;
        int k4 = i & 63;
        int node = node0 + r;
        float4 v = make_float4(0.f, 0.f, 0.f, 0.f);
        if (node < n_nodes)
            v = ((const float4*)h)[(size_t)node * 64 + k4];
        hs4[i] = v;
    }
    __syncthreads();

    const int j     = tid & 127;
    const int rbase = (tid >> 7) * 32;

    float acc[32];
    #pragma unroll
    for (int r = 0; r < 32; r++) acc[r] = 0.f;

    #pragma unroll 1
    for (int k4 = 0; k4 < 64; k4++) {
        const float w0 = Wsh[(4 * k4 + 0) * 128 + j];
        const float w1 = Wsh[(4 * k4 + 1) * 128 + j];
        const float w2 = Wsh[(4 * k4 + 2) * 128 + j];
        const float w3 = Wsh[(4 * k4 + 3) * 128 + j];
        #pragma unroll
        for (int r = 0; r < 32; r++) {
            float4 h4 = hs4[(rbase + r) * 64 + k4];
            acc[r] = fmaf(h4.x, w0, acc[r]);
            acc[r] = fmaf(h4.y, w1, acc[r]);
            acc[r] = fmaf(h4.z, w2, acc[r]);
            acc[r] = fmaf(h4.w, w3, acc[r]);
        }
    }

    // Epilogue: fold b1 into the A half, scatter to g_A / g_B.
    const float bias = (j < 64) ? b1[j] : 0.f;
    #pragma unroll
    for (int r = 0; r < 32; r++) {
        int node = node0 + rbase + r;
        if (node < n_nodes) {
            float v = acc[r] + bias;
            if (j < 64) g_A[(size_t)node * 64 + j]        = v;
            else        g_B[(size_t)node * 64 + (j - 64)] = v;
        }
    }
}

// ---------------------------------------------------------------------------
// Kernel 2: per-edge epilogue. One warp per edge.
//   out[e] = sum_j relu(g_A[u][j] + g_B[v][j]) * W2[j] + b2
// edge_index arrives as int32 (harness downcasts int64 inputs).
// Each lane handles 2 of the 64 hidden channels via float2 (coalesced 256 B
// row reads, mostly L2-resident), then a 5-step shfl butterfly reduction.
// ---------------------------------------------------------------------------
__global__ __launch_bounds__(256)
void edge_kernel(const int* __restrict__ edge_index,
                 const float* __restrict__ W2,
                 const float* __restrict__ b2,
                 float* __restrict__ out,
                 int n_edges)
{
    const int lane = threadIdx.x & 31;
    const int e    = (blockIdx.x * blockDim.x + threadIdx.x) >> 5;
    if (e >= n_edges) return;

    const float w0 = W2[2 * lane + 0];
    const float w1 = W2[2 * lane + 1];

    const int u = edge_index[e];             // source row
    const int v = edge_index[n_edges + e];   // target row

    float2 a = *(const float2*)&g_A[(size_t)u * 64 + 2 * lane];
    float2 b = *(const float2*)&g_B[(size_t)v * 64 + 2 * lane];

    float s0 = fmaxf(a.x + b.x, 0.f);
    float s1 = fmaxf(a.y + b.y, 0.f);
    float p  = fmaf(s0, w0, s1 * w1);

    p += __shfl_xor_sync(0xffffffffu, p, 1);
    p += __shfl_xor_sync(0xffffffffu, p, 2);
    p += __shfl_xor_sync(0xffffffffu, p, 4);
    p += __shfl_xor_sync(0xffffffffu, p, 8);
    p += __shfl_xor_sync(0xffffffffu, p, 16);

    if (lane == 0) out[e] = p + b2[0];
}

// ---------------------------------------------------------------------------
// Launch. Inputs (metadata order): h, edge_index, W1, b1, W2, b2.
// ---------------------------------------------------------------------------
extern "C" void kernel_launch(void* const* d_in, const int* in_sizes, int n_in,
                              void* d_out, int out_size)
{
    const float* h   = (const float*)d_in[0];
    const int*   ei  = (const int*)d_in[1];      // int64 downcast to int32 by harness
    const float* W1  = (const float*)d_in[2];
    const float* b1  = (const float*)d_in[3];
    const float* W2  = (const float*)d_in[4];
    const float* b2  = (const float*)d_in[5];
    float*       out = (float*)d_out;

    const int n_nodes = in_sizes[0] / IN_FEATS;   // 100000
    const int n_edges = out_size;                 // 500000 (output is [E])

    // 128 KB W tile + 64 KB h tile
    const int smem_bytes = (32768 + 16384) * (int)sizeof(float);  // 196608
    cudaFuncSetAttribute(node_gemm_kernel,
                         cudaFuncAttributeMaxDynamicSharedMemorySize, smem_bytes);

    int gemm_blocks = (n_nodes + 63) / 64;
    node_gemm_kernel<<<gemm_blocks, 256, smem_bytes>>>(h, W1, b1, n_nodes);

    // one warp per edge: 8 edges per 256-thread block
    int edge_blocks = (n_edges + 7) / 8;
    edge_kernel<<<edge_blocks, 256>>>(ei, W2, b2, out, n_edges);
}

// round 7
// speedup vs baseline: 2.5535x; 2.5535x over previous
#include <cuda_runtime.h>
#include <cuda_bf16.h>
#include <cstdint>

// Problem constants
#define N_NODES  100000
#define N_EDGES  500000
#define IN_FEATS 256
#define HIDDEN   64

// Fused per-node activations: cols 0..63 = h@W1_top + b1 ("A"), 64..127 = h@W1_bot ("B")
__device__ float g_AB[(size_t)N_NODES * 128];

// Precomputed B operand (Wcat^T as [n=128][k=256] bf16, hi/lo split), pitched rows.
// BP = 264 bf16 per row (256 + 8 pad) -> 128*264 = 33792 ushort = 4224 uint4 each.
__device__ uint4 g_Bh4[4224];
__device__ uint4 g_Bl4[4224];

// Pitches (bf16 units / b32 words). Chosen so pitch_words % 32 == 4 =>
// bank(row,kw) = (4*row + kw) % 32 which is bijective across a warp's
// (groupID 0..7) x (tig 0..3) fragment loads -> conflict-free LDS.
#define AP   136
#define APW  68
#define BP   264
#define BPW  132

// smem byte offsets
#define SM_AH 0
#define SM_AL 34816                       // 128*AP*2
#define SM_BH 69632                       // 2*128*AP*2
#define SM_BL 137216                      // SM_BH + 128*BP*2
#define SM_B1 204800                      // SM_BL + 128*BP*2
#define SMEM_TOTAL 205056                 // + 64 floats of b1

// Split two fp32 into packed bf16 hi and lo (residual) words.
static __device__ __forceinline__ void split2(float a, float b, uint32_t& hi, uint32_t& lo) {
    __nv_bfloat162 h = __floats2bfloat162_rn(a, b);
    float2 hf = __bfloat1622float2(h);
    __nv_bfloat162 l = __floats2bfloat162_rn(a - hf.x, b - hf.y);
    hi = *reinterpret_cast<uint32_t*>(&h);
    lo = *reinterpret_cast<uint32_t*>(&l);
}

// Warp-level bf16 tensor-core MMA, m16n8k16, fp32 accum (sm_80+ baseline PTX).
static __device__ __forceinline__ void mma16816(float* c,
        uint32_t a0, uint32_t a1, uint32_t a2, uint32_t a3,
        uint32_t b0, uint32_t b1) {
    asm volatile(
        "mma.sync.aligned.m16n8k16.row.col.f32.bf16.bf16.f32 "
        "{%0,%1,%2,%3}, {%4,%5,%6,%7}, {%8,%9}, {%0,%1,%2,%3};"
        : "+f"(c[0]), "+f"(c[1]), "+f"(c[2]), "+f"(c[3])
        : "r"(a0), "r"(a1), "r"(a2), "r"(a3), "r"(b0), "r"(b1));
}

// ---------------------------------------------------------------------------
// Kernel 0: build B operand images. B[n][k] = Wcat[k][n]:
//   n<64  -> W1[k*64 + n]
//   n>=64 -> W1[(256+k)*64 + (n-64)]
// ---------------------------------------------------------------------------
__global__ void prep_B(const float* __restrict__ W1) {
    int i = blockIdx.x * 256 + threadIdx.x;       // 32768 = 128 n * 256 k
    int n = i >> 8, k = i & 255;
    float x = (n < 64) ? W1[k * 64 + n] : W1[(256 + k) * 64 + (n - 64)];
    __nv_bfloat16 hb = __float2bfloat16(x);
    __nv_bfloat16 lb = __float2bfloat16(x - __bfloat162float(hb));
    ((unsigned short*)g_Bh4)[n * BP + k] = __bfloat16_as_ushort(hb);
    ((unsigned short*)g_Bl4)[n * BP + k] = __bfloat16_as_ushort(lb);
}

// ---------------------------------------------------------------------------
// Kernel 1: tensor-core node GEMM via warp mma.sync.
// D[128 nodes, 128 cols] per CTA = h_tile @ Wcat, 3-term bf16 split:
//   D = Ahi*Bhi + Ahi*Blo + Alo*Bhi   (fp32 accumulate)
// 8 warps in a 4(M) x 2(N) grid; warp tile 32 x 64 = 2 x 8 m16n8k16 atoms.
// K=256: A staged in 2 chunks of 128; B resident for all 256 k
// (B word index = chunk*64 + chunk-local word — the R6 bug was omitting this).
// ---------------------------------------------------------------------------
__global__ __launch_bounds__(256, 1)
void node_gemm_mma(const float4* __restrict__ h4, const float* __restrict__ b1, int n_nodes)
{
    extern __shared__ char smem[];
    uint32_t*       AHw = (uint32_t*)(smem + SM_AH);
    uint32_t*       ALw = (uint32_t*)(smem + SM_AL);
    const uint32_t* BHw = (const uint32_t*)(smem + SM_BH);
    const uint32_t* BLw = (const uint32_t*)(smem + SM_BL);
    float*          b1s = (float*)(smem + SM_B1);

    const int tid  = threadIdx.x;
    const int wid  = tid >> 5, lane = tid & 31;
    const int gid  = lane >> 2, tig = lane & 3;
    const int wm   = wid >> 1, wn = wid & 1;
    const int node0 = blockIdx.x * 128;

    // Stage B (132 KB, coalesced uint4 copies) + b1.
    {
        uint4* bh = (uint4*)(smem + SM_BH);
        uint4* bl = (uint4*)(smem + SM_BL);
        #pragma unroll 4
        for (int i = tid; i < 4224; i += 256) { bh[i] = g_Bh4[i]; bl[i] = g_Bl4[i]; }
    }
    if (tid < 64) b1s[tid] = b1[tid];

    float c[2][8][4];
    #pragma unroll
    for (int mm = 0; mm < 2; mm++)
        #pragma unroll
        for (int nn = 0; nn < 8; nn++)
            #pragma unroll
            for (int q = 0; q < 4; q++) c[mm][nn][q] = 0.f;

    for (int chunk = 0; chunk < 2; chunk++) {
        __syncthreads();   // B ready (chunk 0) / previous chunk's MMAs done (chunk 1)

        // Stage A chunk: 128 rows x 128 k as bf16 hi/lo, pitched.
        #pragma unroll 2
        for (int t = tid; t < 4096; t += 256) {
            int row = t >> 5, k4 = t & 31;
            int node = node0 + row;
            float4 v = make_float4(0.f, 0.f, 0.f, 0.f);
            if (node < n_nodes) v = h4[(size_t)node * 64 + chunk * 32 + k4];
            uint32_t h0, l0, h1, l1;
            split2(v.x, v.y, h0, l0);
            split2(v.z, v.w, h1, l1);
            *(uint2*)((char*)AHw + row * (AP * 2) + k4 * 8) = make_uint2(h0, h1);
            *(uint2*)((char*)ALw + row * (AP * 2) + k4 * 8) = make_uint2(l0, l1);
        }
        __syncthreads();

        const int r0 = wm * 32 + gid;
        #pragma unroll
        for (int ks = 0; ks < 8; ks++) {
            const int kw  = ks * 8 + tig;          // A: chunk-local word index
            const int bkw = chunk * 64 + kw;       // B: global-k word index (THE FIX)

            uint32_t ah[2][4], al[2][4], bh[8][2], bl[8][2];
            #pragma unroll
            for (int mm = 0; mm < 2; mm++) {
                int ra = r0 + mm * 16;
                ah[mm][0] = AHw[ra * APW + kw];
                ah[mm][1] = AHw[(ra + 8) * APW + kw];
                ah[mm][2] = AHw[ra * APW + kw + 4];
                ah[mm][3] = AHw[(ra + 8) * APW + kw + 4];
                al[mm][0] = ALw[ra * APW + kw];
                al[mm][1] = ALw[(ra + 8) * APW + kw];
                al[mm][2] = ALw[ra * APW + kw + 4];
                al[mm][3] = ALw[(ra + 8) * APW + kw + 4];
            }
            #pragma unroll
            for (int nn = 0; nn < 8; nn++) {
                int n = wn * 64 + nn * 8 + gid;
                bh[nn][0] = BHw[n * BPW + bkw];
                bh[nn][1] = BHw[n * BPW + bkw + 4];
                bl[nn][0] = BLw[n * BPW + bkw];
                bl[nn][1] = BLw[n * BPW + bkw + 4];
            }

            // Term order keeps 16 independent accumulators between reuses.
            #pragma unroll
            for (int mm = 0; mm < 2; mm++)
                #pragma unroll
                for (int nn = 0; nn < 8; nn++)
                    mma16816(c[mm][nn], ah[mm][0], ah[mm][1], ah[mm][2], ah[mm][3],
                             bh[nn][0], bh[nn][1]);
            #pragma unroll
            for (int mm = 0; mm < 2; mm++)
                #pragma unroll
                for (int nn = 0; nn < 8; nn++)
                    mma16816(c[mm][nn], ah[mm][0], ah[mm][1], ah[mm][2], ah[mm][3],
                             bl[nn][0], bl[nn][1]);
            #pragma unroll
            for (int mm = 0; mm < 2; mm++)
                #pragma unroll
                for (int nn = 0; nn < 8; nn++)
                    mma16816(c[mm][nn], al[mm][0], al[mm][1], al[mm][2], al[mm][3],
                             bh[nn][0], bh[nn][1]);
        }
    }

    // Epilogue: fold b1 into cols<64 (exactly warps with wn==0), write g_AB rows.
    #pragma unroll
    for (int mm = 0; mm < 2; mm++) {
        #pragma unroll
        for (int nn = 0; nn < 8; nn++) {
            int col = wn * 64 + nn * 8 + tig * 2;
            float bx = 0.f, by = 0.f;
            if (wn == 0) { bx = b1s[col]; by = b1s[col + 1]; }
            int na = node0 + wm * 32 + mm * 16 + gid;   // rows groupID / groupID+8
            if (na < n_nodes)
                *(float2*)&g_AB[(size_t)na * 128 + col] =
                    make_float2(c[mm][nn][0] + bx, c[mm][nn][1] + by);
            int nb = na + 8;
            if (nb < n_nodes)
                *(float2*)&g_AB[(size_t)nb * 128 + col] =
                    make_float2(c[mm][nn][2] + bx, c[mm][nn][3] + by);
        }
    }
}

// ---------------------------------------------------------------------------
// Kernel 2: per-edge epilogue, 4 edges per warp (8 gathers in flight for
// L2-latency hiding). out[e] = sum_j relu(A[u][j] + B[v][j]) * W2[j] + b2.
// ---------------------------------------------------------------------------
__global__ __launch_bounds__(256)
void edge_kernel(const int* __restrict__ ei, const float* __restrict__ W2,
                 const float* __restrict__ b2, float* __restrict__ out, int n_edges)
{
    const int lane = threadIdx.x & 31;
    const int w = (blockIdx.x * blockDim.x + threadIdx.x) >> 5;
    const int e0 = w * 4;
    if (e0 >= n_edges) return;

    const float w0 = W2[2 * lane + 0];
    const float w1 = W2[2 * lane + 1];
    const float bias = b2[0];

    float2 a[4], b[4];
    #pragma unroll
    for (int i = 0; i < 4; i++) {
        int e = e0 + i; if (e > n_edges - 1) e = n_edges - 1;   // clamp keeps loads batched
        int u = ei[e];
        int v = ei[n_edges + e];
        a[i] = *(const float2*)&g_AB[(size_t)u * 128 + 2 * lane];
        b[i] = *(const float2*)&g_AB[(size_t)v * 128 + 64 + 2 * lane];
    }
    #pragma unroll
    for (int i = 0; i < 4; i++) {
        float s0 = fmaxf(a[i].x + b[i].x, 0.f);
        float s1 = fmaxf(a[i].y + b[i].y, 0.f);
        float p = fmaf(s0, w0, s1 * w1);
        p += __shfl_xor_sync(0xffffffffu, p, 1);
        p += __shfl_xor_sync(0xffffffffu, p, 2);
        p += __shfl_xor_sync(0xffffffffu, p, 4);
        p += __shfl_xor_sync(0xffffffffu, p, 8);
        p += __shfl_xor_sync(0xffffffffu, p, 16);
        if (lane == 0 && e0 + i < n_edges) out[e0 + i] = p + bias;
    }
}

// ---------------------------------------------------------------------------
// Launch. Inputs (metadata order): h, edge_index (int32), W1, b1, W2, b2.
// ---------------------------------------------------------------------------
extern "C" void kernel_launch(void* const* d_in, const int* in_sizes, int n_in,
                              void* d_out, int out_size)
{
    const float* h   = (const float*)d_in[0];
    const int*   ei  = (const int*)d_in[1];
    const float* W1  = (const float*)d_in[2];
    const float* b1  = (const float*)d_in[3];
    const float* W2  = (const float*)d_in[4];
    const float* b2  = (const float*)d_in[5];
    float*       out = (float*)d_out;

    const int n_nodes = in_sizes[0] / IN_FEATS;   // 100000
    const int n_edges = out_size;                 // 500000

    prep_B<<<128, 256>>>(W1);

    cudaFuncSetAttribute(node_gemm_mma,
                         cudaFuncAttributeMaxDynamicSharedMemorySize, SMEM_TOTAL);
    int gemm_blocks = (n_nodes + 127) / 128;
    node_gemm_mma<<<gemm_blocks, 256, SMEM_TOTAL>>>((const float4*)h, b1, n_nodes);

    int edge_blocks = (n_edges + 31) / 32;        // 32 edges per 256-thread block
    edge_kernel<<<edge_blocks, 256>>>(ei, W2, b2, out, n_edges);
}

// round 9
// speedup vs baseline: 3.2964x; 1.2909x over previous
#include <cuda_runtime.h>
#include <cuda_bf16.h>
#include <cstdint>

// Problem constants
#define N_NODES  100000
#define N_EDGES  500000
#define IN_FEATS 256
#define HIDDEN   64

// Fused per-node activations: cols 0..63 = h@W1_top + b1 ("A"), 64..127 = h@W1_bot ("B")
__device__ float g_AB[(size_t)N_NODES * 128];

// Precomputed B operand (Wcat^T as [n=128][k=256] bf16, hi/lo split), pitched rows.
// BP = 264 bf16/row (256 + 8 pad) -> 128*264*2 B = 67584 B = 4224 uint4 each.
__device__ uint4 g_Bh4[4224];
__device__ uint4 g_Bl4[4224];

#define BP   264        // B pitch in bf16 (row = 528 B; 132 words % 32 == 4 -> LDSM conflict-free)
#define APB  144        // A pitch in bytes  (72 bf16; 36 words % 32 == 4 -> LDSM conflict-free)

// smem byte offsets: B hi | B lo | A buf0 hi | buf0 lo | buf1 hi | buf1 lo | b1
#define SM_BH   0
#define SM_BL   67584
#define SM_A0H  135168
#define SM_A0L  153600
#define SM_A1H  172032
#define SM_A1L  190464
#define SM_B1   208896
#define SMEM_TOTAL 209152

static __device__ __forceinline__ uint32_t smem_u32(const void* p) {
    uint32_t a;
    asm("{ .reg .u64 t; cvta.to.shared.u64 t, %1; cvt.u32.u64 %0, t; }" : "=r"(a) : "l"(p));
    return a;
}

// Split two fp32 into packed bf16 hi and lo (residual) words.
static __device__ __forceinline__ void split2(float a, float b, uint32_t& hi, uint32_t& lo) {
    __nv_bfloat162 h = __floats2bfloat162_rn(a, b);
    float2 hf = __bfloat1622float2(h);
    __nv_bfloat162 l = __floats2bfloat162_rn(a - hf.x, b - hf.y);
    hi = *reinterpret_cast<uint32_t*>(&h);
    lo = *reinterpret_cast<uint32_t*>(&l);
}

static __device__ __forceinline__ void ldsm4(uint32_t* r, uint32_t addr) {
    asm volatile("ldmatrix.sync.aligned.m8n8.x4.shared.b16 {%0,%1,%2,%3}, [%4];"
        : "=r"(r[0]), "=r"(r[1]), "=r"(r[2]), "=r"(r[3]) : "r"(addr));
}

static __device__ __forceinline__ void mma16816(float* c,
        const uint32_t* a, uint32_t b0, uint32_t b1) {
    asm volatile(
        "mma.sync.aligned.m16n8k16.row.col.f32.bf16.bf16.f32 "
        "{%0,%1,%2,%3}, {%4,%5,%6,%7}, {%8,%9}, {%0,%1,%2,%3};"
        : "+f"(c[0]), "+f"(c[1]), "+f"(c[2]), "+f"(c[3])
        : "r"(a[0]), "r"(a[1]), "r"(a[2]), "r"(a[3]), "r"(b0), "r"(b1));
}

// ---------------------------------------------------------------------------
// Kernel 0: build B operand images. B[n][k] = Wcat[k][n]:
//   n<64 -> W1[k*64+n];  n>=64 -> W1[(256+k)*64 + (n-64)]
// ---------------------------------------------------------------------------
__global__ void prep_B(const float* __restrict__ W1) {
    int i = blockIdx.x * 256 + threadIdx.x;       // 32768 = 128 n * 256 k
    int n = i >> 8, k = i & 255;
    float x = (n < 64) ? W1[k * 64 + n] : W1[(256 + k) * 64 + (n - 64)];
    __nv_bfloat16 hb = __float2bfloat16(x);
    __nv_bfloat16 lb = __float2bfloat16(x - __bfloat162float(hb));
    ((unsigned short*)g_Bh4)[n * BP + k] = __bfloat16_as_ushort(hb);
    ((unsigned short*)g_Bl4)[n * BP + k] = __bfloat16_as_ushort(lb);
}

// ---------------------------------------------------------------------------
// Kernel 1: tensor-core node GEMM. D[128,128] per CTA, 3-term bf16 split:
//   D = Ahi*Bhi + Ahi*Blo + Alo*Bhi  (fp32 accum)
// 8 warps (4M x 2N), warp tile 32x64. K=256 as 4 chunks of 64 with
// double-buffered A smem; next chunk's ldg overlapped with current MMAs.
// All fragment loads via ldmatrix.x4, conflict-free pitches.
// ---------------------------------------------------------------------------
__global__ __launch_bounds__(256, 1)
void node_gemm_mma(const float4* __restrict__ h4, const float* __restrict__ b1, int n_nodes)
{
    extern __shared__ char smem[];
    const uint32_t sb = smem_u32(smem);
    float* b1s = (float*)(smem + SM_B1);

    const int tid  = threadIdx.x;
    const int wid  = tid >> 5, lane = tid & 31;
    const int gid  = lane >> 2, tig = lane & 3;
    const int wm   = wid >> 1, wn = wid & 1;
    const int node0 = blockIdx.x * 128;

    // Stage B (132 KB, coalesced uint4) + b1.
    {
        uint4* bh = (uint4*)(smem + SM_BH);
        uint4* bl = (uint4*)(smem + SM_BL);
        #pragma unroll 4
        for (int i = tid; i < 4224; i += 256) { bh[i] = g_Bh4[i]; bl[i] = g_Bl4[i]; }
    }
    if (tid < 64) b1s[tid] = b1[tid];

    // ldmatrix lane addressing.
    const int r8 = lane & 7;
    // A x4: m0=(rows+0..7,k0-7) m1=(rows+8..15,k0-7) m2=(rows,k8-15) m3=(rows+8,k8-15)
    const uint32_t a_off = (uint32_t)((wm * 32 + (((lane >> 3) & 1) << 3) + r8) * APB
                                      + (((lane >> 4) & 1) << 4));
    // B x4 (per n-pair): m0=(n+0..7,k0-7) m1=(n,k8-15) m2=(n+8..15,k0-7) m3=(n+8,k8-15)
    const uint32_t b_row = (uint32_t)(wn * 64 + ((lane >> 4) << 3) + r8);
    const uint32_t b_off = b_row * (BP * 2) + (((lane >> 3) & 1) << 4);
    const uint32_t baseBH = sb + SM_BH + b_off;
    const uint32_t baseBL = sb + SM_BL + b_off;

    const uint32_t abufH[2] = { sb + SM_A0H + a_off, sb + SM_A1H + a_off };
    const uint32_t abufL[2] = { sb + SM_A0L + a_off, sb + SM_A1L + a_off };

    // Staging map: fixed float4 column per thread, 8 rows spaced 16.
    const int s_f4  = tid & 15;            // 0..15 (64 k = 16 float4)
    const int s_row0 = tid >> 4;           // 0..15

    float c[2][8][4];
    #pragma unroll
    for (int mm = 0; mm < 2; mm++)
        #pragma unroll
        for (int nn = 0; nn < 8; nn++)
            #pragma unroll
            for (int q = 0; q < 4; q++) c[mm][nn][q] = 0.f;

    // Prologue: stage chunk 0 into buffer 0.
    {
        #pragma unroll
        for (int j = 0; j < 8; j++) {
            int row = s_row0 + j * 16;
            int node = node0 + row;
            float4 v = make_float4(0.f, 0.f, 0.f, 0.f);
            if (node < n_nodes) v = h4[(size_t)node * 64 + s_f4];
            uint32_t h0, l0, h1, l1;
            split2(v.x, v.y, h0, l0);
            split2(v.z, v.w, h1, l1);
            *(uint2*)(smem + SM_A0H + row * APB + s_f4 * 8) = make_uint2(h0, h1);
            *(uint2*)(smem + SM_A0L + row * APB + s_f4 * 8) = make_uint2(l0, l1);
        }
    }
    __syncthreads();

    for (int chunk = 0; chunk < 4; chunk++) {
        const int buf = chunk & 1;
        const bool more = (chunk + 1) < 4;

        // Issue next chunk's global loads early (latency hidden by MMA block).
        float4 pf[8];
        if (more) {
            #pragma unroll
            for (int j = 0; j < 8; j++) {
                int node = node0 + s_row0 + j * 16;
                pf[j] = make_float4(0.f, 0.f, 0.f, 0.f);
                if (node < n_nodes)
                    pf[j] = h4[(size_t)node * 64 + (chunk + 1) * 16 + s_f4];
            }
        }

        // MMA over this chunk (4 k16-steps).
        #pragma unroll
        for (int ks = 0; ks < 4; ks++) {
            const uint32_t akb = (uint32_t)(ks * 32);
            const uint32_t bkb = (uint32_t)(chunk * 128 + ks * 32);

            uint32_t ah[2][4], al[2][4], bh[4][4], bl[4][4];
            ldsm4(ah[0], abufH[buf] + akb);
            ldsm4(ah[1], abufH[buf] + 16 * APB + akb);
            ldsm4(al[0], abufL[buf] + akb);
            ldsm4(al[1], abufL[buf] + 16 * APB + akb);
            #pragma unroll
            for (int p = 0; p < 4; p++) {
                ldsm4(bh[p], baseBH + (uint32_t)(p * 16 * BP * 2) + bkb);
                ldsm4(bl[p], baseBL + (uint32_t)(p * 16 * BP * 2) + bkb);
            }

            // 16 independent accumulators between reuses in each term sweep.
            #pragma unroll
            for (int mm = 0; mm < 2; mm++)
                #pragma unroll
                for (int nn = 0; nn < 8; nn++)
                    mma16816(c[mm][nn], ah[mm], bh[nn >> 1][(nn & 1) * 2],
                             bh[nn >> 1][(nn & 1) * 2 + 1]);
            #pragma unroll
            for (int mm = 0; mm < 2; mm++)
                #pragma unroll
                for (int nn = 0; nn < 8; nn++)
                    mma16816(c[mm][nn], ah[mm], bl[nn >> 1][(nn & 1) * 2],
                             bl[nn >> 1][(nn & 1) * 2 + 1]);
            #pragma unroll
            for (int mm = 0; mm < 2; mm++)
                #pragma unroll
                for (int nn = 0; nn < 8; nn++)
                    mma16816(c[mm][nn], al[mm], bh[nn >> 1][(nn & 1) * 2],
                             bh[nn >> 1][(nn & 1) * 2 + 1]);
        }

        // Convert + store next chunk into the other buffer.
        if (more) {
            const int hb = SM_A0H + (1 - buf) * (SM_A1H - SM_A0H);
            const int lb = SM_A0L + (1 - buf) * (SM_A1H - SM_A0H);
            #pragma unroll
            for (int j = 0; j < 8; j++) {
                int row = s_row0 + j * 16;
                uint32_t h0, l0, h1, l1;
                split2(pf[j].x, pf[j].y, h0, l0);
                split2(pf[j].z, pf[j].w, h1, l1);
                *(uint2*)(smem + hb + row * APB + s_f4 * 8) = make_uint2(h0, h1);
                *(uint2*)(smem + lb + row * APB + s_f4 * 8) = make_uint2(l0, l1);
            }
            __syncthreads();
        }
    }

    // Epilogue: fold b1 into cols<64 (warps with wn==0), write g_AB rows.
    #pragma unroll
    for (int mm = 0; mm < 2; mm++) {
        #pragma unroll
        for (int nn = 0; nn < 8; nn++) {
            int col = wn * 64 + nn * 8 + tig * 2;
            float bx = 0.f, by = 0.f;
            if (wn == 0) { bx = b1s[col]; by = b1s[col + 1]; }
            int na = node0 + wm * 32 + mm * 16 + gid;
            if (na < n_nodes)
                *(float2*)&g_AB[(size_t)na * 128 + col] =
                    make_float2(c[mm][nn][0] + bx, c[mm][nn][1] + by);
            int nb = na + 8;
            if (nb < n_nodes)
                *(float2*)&g_AB[(size_t)nb * 128 + col] =
                    make_float2(c[mm][nn][2] + bx, c[mm][nn][3] + by);
        }
    }
}

// ---------------------------------------------------------------------------
// Kernel 2: per-edge epilogue, 4 edges per warp (8 gathers in flight).
// out[e] = sum_j relu(A[u][j] + B[v][j]) * W2[j] + b2.
// ---------------------------------------------------------------------------
__global__ __launch_bounds__(256)
void edge_kernel(const int* __restrict__ ei, const float* __restrict__ W2,
                 const float* __restrict__ b2, float* __restrict__ out, int n_edges)
{
    const int lane = threadIdx.x & 31;
    const int w = (blockIdx.x * blockDim.x + threadIdx.x) >> 5;
    const int e0 = w * 4;
    if (e0 >= n_edges) return;

    const float w0 = W2[2 * lane + 0];
    const float w1 = W2[2 * lane + 1];
    const float bias = b2[0];

    float2 a[4], b[4];
    #pragma unroll
    for (int i = 0; i < 4; i++) {
        int e = e0 + i; if (e > n_edges - 1) e = n_edges - 1;
        int u = ei[e];
        int v = ei[n_edges + e];
        a[i] = *(const float2*)&g_AB[(size_t)u * 128 + 2 * lane];
        b[i] = *(const float2*)&g_AB[(size_t)v * 128 + 64 + 2 * lane];
    }
    #pragma unroll
    for (int i = 0; i < 4; i++) {
        float s0 = fmaxf(a[i].x + b[i].x, 0.f);
        float s1 = fmaxf(a[i].y + b[i].y, 0.f);
        float p = fmaf(s0, w0, s1 * w1);
        p += __shfl_xor_sync(0xffffffffu, p, 1);
        p += __shfl_xor_sync(0xffffffffu, p, 2);
        p += __shfl_xor_sync(0xffffffffu, p, 4);
        p += __shfl_xor_sync(0xffffffffu, p, 8);
        p += __shfl_xor_sync(0xffffffffu, p, 16);
        if (lane == 0 && e0 + i < n_edges) out[e0 + i] = p + bias;
    }
}

// ---------------------------------------------------------------------------
// Launch. Inputs (metadata order): h, edge_index (int32), W1, b1, W2, b2.
// ---------------------------------------------------------------------------
extern "C" void kernel_launch(void* const* d_in, const int* in_sizes, int n_in,
                              void* d_out, int out_size)
{
    const float* h   = (const float*)d_in[0];
    const int*   ei  = (const int*)d_in[1];
    const float* W1  = (const float*)d_in[2];
    const float* b1  = (const float*)d_in[3];
    const float* W2  = (const float*)d_in[4];
    const float* b2  = (const float*)d_in[5];
    float*       out = (float*)d_out;

    const int n_nodes = in_sizes[0] / IN_FEATS;   // 100000
    const int n_edges = out_size;                 // 500000

    prep_B<<<128, 256>>>(W1);

    cudaFuncSetAttribute(node_gemm_mma,
                         cudaFuncAttributeMaxDynamicSharedMemorySize, SMEM_TOTAL);
    int gemm_blocks = (n_nodes + 127) / 128;
    node_gemm_mma<<<gemm_blocks, 256, SMEM_TOTAL>>>((const float4*)h, b1, n_nodes);

    int edge_blocks = (n_edges + 31) / 32;        // 32 edges per 256-thread block
    edge_kernel<<<edge_blocks, 256>>>(ei, W2, b2, out, n_edges);
}

// round 10
// speedup vs baseline: 3.3897x; 1.0283x over previous
#include <cuda_runtime.h>
#include <cuda_bf16.h>
#include <cstdint>

// Problem constants
#define N_NODES  100000
#define N_EDGES  500000
#define IN_FEATS 256
#define HIDDEN   64
#define NSM      148

// Fused per-node activations: cols 0..63 = h@W1_top + b1 ("A"), 64..127 = h@W1_bot ("B")
__device__ float g_AB[(size_t)N_NODES * 128];

#define BP   264        // B pitch in bf16 (row = 528 B; 132 words % 32 == 4 -> LDSM conflict-free)
#define APB  144        // A pitch in bytes  (72 bf16; 36 words % 32 == 4 -> LDSM conflict-free)

// smem byte offsets: B hi | B lo | A buf0 hi | buf0 lo | buf1 hi | buf1 lo | b1
#define SM_BH   0
#define SM_BL   67584
#define SM_A0H  135168
#define SM_A0L  153600
#define SM_A1H  172032
#define SM_A1L  190464
#define SM_B1   208896
#define SMEM_TOTAL 209152

static __device__ __forceinline__ uint32_t smem_u32(const void* p) {
    uint32_t a;
    asm("{ .reg .u64 t; cvta.to.shared.u64 t, %1; cvt.u32.u64 %0, t; }" : "=r"(a) : "l"(p));
    return a;
}

// Split two fp32 into packed bf16 hi and lo (residual) words.
static __device__ __forceinline__ void split2(float a, float b, uint32_t& hi, uint32_t& lo) {
    __nv_bfloat162 h = __floats2bfloat162_rn(a, b);
    float2 hf = __bfloat1622float2(h);
    __nv_bfloat162 l = __floats2bfloat162_rn(a - hf.x, b - hf.y);
    hi = *reinterpret_cast<uint32_t*>(&h);
    lo = *reinterpret_cast<uint32_t*>(&l);
}

static __device__ __forceinline__ void ldsm4(uint32_t* r, uint32_t addr) {
    asm volatile("ldmatrix.sync.aligned.m8n8.x4.shared.b16 {%0,%1,%2,%3}, [%4];"
        : "=r"(r[0]), "=r"(r[1]), "=r"(r[2]), "=r"(r[3]) : "r"(addr));
}

static __device__ __forceinline__ void mma16816(float* c,
        const uint32_t* a, uint32_t b0, uint32_t b1) {
    asm volatile(
        "mma.sync.aligned.m16n8k16.row.col.f32.bf16.bf16.f32 "
        "{%0,%1,%2,%3}, {%4,%5,%6,%7}, {%8,%9}, {%0,%1,%2,%3};"
        : "+f"(c[0]), "+f"(c[1]), "+f"(c[2]), "+f"(c[3])
        : "r"(a[0]), "r"(a[1]), "r"(a[2]), "r"(a[3]), "r"(b0), "r"(b1));
}

// ---------------------------------------------------------------------------
// Kernel 1: PERSISTENT tensor-core node GEMM. Each CTA builds the B operand
// (Wcat^T hi/lo bf16, pitched) in smem ONCE from W1, then loops over
// 128-node tiles: D = Ahi*Bhi + Ahi*Blo + Alo*Bhi (fp32 accum).
// 8 warps (4M x 2N), warp tile 32x64; K=256 as 4 chunks of 64 with
// double-buffered A smem; next chunk's ldg overlapped with current MMAs.
// ---------------------------------------------------------------------------
__global__ __launch_bounds__(256, 1)
void node_gemm_mma(const float4* __restrict__ h4, const float* __restrict__ W1,
                   const float* __restrict__ b1, int n_nodes, int n_tiles)
{
    extern __shared__ char smem[];
    const uint32_t sb = smem_u32(smem);
    float* b1s = (float*)(smem + SM_B1);

    const int tid  = threadIdx.x;
    const int wid  = tid >> 5, lane = tid & 31;
    const int gid  = lane >> 2, tig = lane & 3;
    const int wm   = wid >> 1, wn = wid & 1;

    // Build B images in smem once: B[n][k] = Wcat[k][n].
    //   n<64 -> W1[k*64+n];  n>=64 -> W1[(256+k)*64 + (n-64)]
    // n fastest within a warp -> coalesced W1 reads.
    {
        unsigned short* BH = (unsigned short*)(smem + SM_BH);
        unsigned short* BL = (unsigned short*)(smem + SM_BL);
        #pragma unroll 8
        for (int i = tid; i < 32768; i += 256) {
            int n = i & 127, k = i >> 7;
            float x = (n < 64) ? W1[k * 64 + n] : W1[(256 + k) * 64 + (n - 64)];
            __nv_bfloat16 hb = __float2bfloat16(x);
            __nv_bfloat16 lb = __float2bfloat16(x - __bfloat162float(hb));
            BH[n * BP + k] = __bfloat16_as_ushort(hb);
            BL[n * BP + k] = __bfloat16_as_ushort(lb);
        }
    }
    if (tid < 64) b1s[tid] = b1[tid];

    // ldmatrix lane addressing.
    const int r8 = lane & 7;
    const uint32_t a_off = (uint32_t)((wm * 32 + (((lane >> 3) & 1) << 3) + r8) * APB
                                      + (((lane >> 4) & 1) << 4));
    const uint32_t b_row = (uint32_t)(wn * 64 + ((lane >> 4) << 3) + r8);
    const uint32_t b_off = b_row * (BP * 2) + (((lane >> 3) & 1) << 4);
    const uint32_t baseBH = sb + SM_BH + b_off;
    const uint32_t baseBL = sb + SM_BL + b_off;

    const uint32_t abufH[2] = { sb + SM_A0H + a_off, sb + SM_A1H + a_off };
    const uint32_t abufL[2] = { sb + SM_A0L + a_off, sb + SM_A1L + a_off };

    // Staging map: fixed float4 column per thread, 8 rows spaced 16.
    const int s_f4   = tid & 15;           // 0..15 (64 k = 16 float4)
    const int s_row0 = tid >> 4;           // 0..15

    for (int tile = blockIdx.x; tile < n_tiles; tile += gridDim.x) {
        const int node0 = tile * 128;

        float c[2][8][4];
        #pragma unroll
        for (int mm = 0; mm < 2; mm++)
            #pragma unroll
            for (int nn = 0; nn < 8; nn++)
                #pragma unroll
                for (int q = 0; q < 4; q++) c[mm][nn][q] = 0.f;

        // Prologue: stage chunk 0 into buffer 0.
        #pragma unroll
        for (int j = 0; j < 8; j++) {
            int row = s_row0 + j * 16;
            int node = node0 + row;
            float4 v = make_float4(0.f, 0.f, 0.f, 0.f);
            if (node < n_nodes) v = h4[(size_t)node * 64 + s_f4];
            uint32_t h0, l0, h1, l1;
            split2(v.x, v.y, h0, l0);
            split2(v.z, v.w, h1, l1);
            *(uint2*)(smem + SM_A0H + row * APB + s_f4 * 8) = make_uint2(h0, h1);
            *(uint2*)(smem + SM_A0L + row * APB + s_f4 * 8) = make_uint2(l0, l1);
        }
        __syncthreads();   // (also orders the one-time B build before first MMAs)

        for (int chunk = 0; chunk < 4; chunk++) {
            const int buf = chunk & 1;
            const bool more = (chunk + 1) < 4;

            // Issue next chunk's global loads early (latency hidden by MMAs).
            float4 pf[8];
            if (more) {
                #pragma unroll
                for (int j = 0; j < 8; j++) {
                    int node = node0 + s_row0 + j * 16;
                    pf[j] = make_float4(0.f, 0.f, 0.f, 0.f);
                    if (node < n_nodes)
                        pf[j] = h4[(size_t)node * 64 + (chunk + 1) * 16 + s_f4];
                }
            }

            // MMA over this chunk (4 k16-steps).
            #pragma unroll
            for (int ks = 0; ks < 4; ks++) {
                const uint32_t akb = (uint32_t)(ks * 32);
                const uint32_t bkb = (uint32_t)(chunk * 128 + ks * 32);

                uint32_t ah[2][4], al[2][4], bh[4][4], bl[4][4];
                ldsm4(ah[0], abufH[buf] + akb);
                ldsm4(ah[1], abufH[buf] + 16 * APB + akb);
                ldsm4(al[0], abufL[buf] + akb);
                ldsm4(al[1], abufL[buf] + 16 * APB + akb);
                #pragma unroll
                for (int p = 0; p < 4; p++) {
                    ldsm4(bh[p], baseBH + (uint32_t)(p * 16 * BP * 2) + bkb);
                    ldsm4(bl[p], baseBL + (uint32_t)(p * 16 * BP * 2) + bkb);
                }

                #pragma unroll
                for (int mm = 0; mm < 2; mm++)
                    #pragma unroll
                    for (int nn = 0; nn < 8; nn++)
                        mma16816(c[mm][nn], ah[mm], bh[nn >> 1][(nn & 1) * 2],
                                 bh[nn >> 1][(nn & 1) * 2 + 1]);
                #pragma unroll
                for (int mm = 0; mm < 2; mm++)
                    #pragma unroll
                    for (int nn = 0; nn < 8; nn++)
                        mma16816(c[mm][nn], ah[mm], bl[nn >> 1][(nn & 1) * 2],
                                 bl[nn >> 1][(nn & 1) * 2 + 1]);
                #pragma unroll
                for (int mm = 0; mm < 2; mm++)
                    #pragma unroll
                    for (int nn = 0; nn < 8; nn++)
                        mma16816(c[mm][nn], al[mm], bh[nn >> 1][(nn & 1) * 2],
                                 bh[nn >> 1][(nn & 1) * 2 + 1]);
            }

            // Convert + store next chunk into the other buffer.
            if (more) {
                const int hb = SM_A0H + (1 - buf) * (SM_A1H - SM_A0H);
                const int lb = SM_A0L + (1 - buf) * (SM_A1H - SM_A0H);
                #pragma unroll
                for (int j = 0; j < 8; j++) {
                    int row = s_row0 + j * 16;
                    uint32_t h0, l0, h1, l1;
                    split2(pf[j].x, pf[j].y, h0, l0);
                    split2(pf[j].z, pf[j].w, h1, l1);
                    *(uint2*)(smem + hb + row * APB + s_f4 * 8) = make_uint2(h0, h1);
                    *(uint2*)(smem + lb + row * APB + s_f4 * 8) = make_uint2(l0, l1);
                }
                __syncthreads();
            }
        }

        // Epilogue: fold b1 into cols<64 (warps with wn==0), write g_AB rows.
        // (Next tile's prologue writes buf0, last read before the chunk-3
        // staging sync; chunk-3 MMAs read buf1 — disjoint, race-free.)
        #pragma unroll
        for (int mm = 0; mm < 2; mm++) {
            #pragma unroll
            for (int nn = 0; nn < 8; nn++) {
                int col = wn * 64 + nn * 8 + tig * 2;
                float bx = 0.f, by = 0.f;
                if (wn == 0) { bx = b1s[col]; by = b1s[col + 1]; }
                int na = node0 + wm * 32 + mm * 16 + gid;
                if (na < n_nodes)
                    *(float2*)&g_AB[(size_t)na * 128 + col] =
                        make_float2(c[mm][nn][0] + bx, c[mm][nn][1] + by);
                int nb = na + 8;
                if (nb < n_nodes)
                    *(float2*)&g_AB[(size_t)nb * 128 + col] =
                        make_float2(c[mm][nn][2] + bx, c[mm][nn][3] + by);
            }
        }
    }
}

// ---------------------------------------------------------------------------
// Kernel 2: per-edge epilogue, 8 edges per warp (16 gathers in flight).
// out[e] = sum_j relu(A[u][j] + B[v][j]) * W2[j] + b2.
// ---------------------------------------------------------------------------
__global__ __launch_bounds__(256)
void edge_kernel(const int* __restrict__ ei, const float* __restrict__ W2,
                 const float* __restrict__ b2, float* __restrict__ out, int n_edges)
{
    const int lane = threadIdx.x & 31;
    const int w = (blockIdx.x * blockDim.x + threadIdx.x) >> 5;
    const int e0 = w * 8;
    if (e0 >= n_edges) return;

    const float w0 = W2[2 * lane + 0];
    const float w1 = W2[2 * lane + 1];
    const float bias = b2[0];

    float2 a[8], b[8];
    #pragma unroll
    for (int i = 0; i < 8; i++) {
        int e = e0 + i; if (e > n_edges - 1) e = n_edges - 1;   // clamp keeps loads batched
        int u = ei[e];
        int v = ei[n_edges + e];
        a[i] = *(const float2*)&g_AB[(size_t)u * 128 + 2 * lane];
        b[i] = *(const float2*)&g_AB[(size_t)v * 128 + 64 + 2 * lane];
    }
    #pragma unroll
    for (int i = 0; i < 8; i++) {
        float s0 = fmaxf(a[i].x + b[i].x, 0.f);
        float s1 = fmaxf(a[i].y + b[i].y, 0.f);
        float p = fmaf(s0, w0, s1 * w1);
        p += __shfl_xor_sync(0xffffffffu, p, 1);
        p += __shfl_xor_sync(0xffffffffu, p, 2);
        p += __shfl_xor_sync(0xffffffffu, p, 4);
        p += __shfl_xor_sync(0xffffffffu, p, 8);
        p += __shfl_xor_sync(0xffffffffu, p, 16);
        if (lane == 0 && e0 + i < n_edges) out[e0 + i] = p + bias;
    }
}

// ---------------------------------------------------------------------------
// Launch. Inputs (metadata order): h, edge_index (int32), W1, b1, W2, b2.
// ---------------------------------------------------------------------------
extern "C" void kernel_launch(void* const* d_in, const int* in_sizes, int n_in,
                              void* d_out, int out_size)
{
    const float* h   = (const float*)d_in[0];
    const int*   ei  = (const int*)d_in[1];
    const float* W1  = (const float*)d_in[2];
    const float* b1  = (const float*)d_in[3];
    const float* W2  = (const float*)d_in[4];
    const float* b2  = (const float*)d_in[5];
    float*       out = (float*)d_out;

    const int n_nodes = in_sizes[0] / IN_FEATS;   // 100000
    const int n_edges = out_size;                 // 500000
    const int n_tiles = (n_nodes + 127) / 128;    // 782

    cudaFuncSetAttribute(node_gemm_mma,
                         cudaFuncAttributeMaxDynamicSharedMemorySize, SMEM_TOTAL);
    int gemm_blocks = n_tiles < NSM ? n_tiles : NSM;
    node_gemm_mma<<<gemm_blocks, 256, SMEM_TOTAL>>>((const float4*)h, W1, b1,
                                                    n_nodes, n_tiles);

    int edge_blocks = (n_edges + 63) / 64;        // 64 edges per 256-thread block
    edge_kernel<<<edge_blocks, 256>>>(ei, W2, b2, out, n_edges);
}

// round 11
// speedup vs baseline: 5.0460x; 1.4886x over previous
#include <cuda_runtime.h>
#include <cuda_fp16.h>
#include <cstdint>

// Problem constants
#define N_NODES  100000
#define N_EDGES  500000
#define IN_FEATS 256
#define HIDDEN   64
#define NSM      148

// Fused per-node activations: cols 0..63 = h@W1_top + b1 ("A"), 64..127 = h@W1_bot ("B")
__device__ float g_AB[(size_t)N_NODES * 128];

#define BP   264        // B pitch in fp16 (row = 528 B; 132 words % 32 == 4 -> LDSM conflict-free)
#define APB  144        // A pitch in bytes (72 fp16; 36 words % 32 == 4 -> LDSM conflict-free)

// smem byte offsets: B hi | B lo | A buf0 | A buf1 | b1
#define SM_BH   0
#define SM_BL   67584
#define SM_A0   135168
#define SM_A1   153600
#define SM_B1   172032
#define SMEM_TOTAL 172288

static __device__ __forceinline__ uint32_t smem_u32(const void* p) {
    uint32_t a;
    asm("{ .reg .u64 t; cvta.to.shared.u64 t, %1; cvt.u32.u64 %0, t; }" : "=r"(a) : "l"(p));
    return a;
}

static __device__ __forceinline__ void ldsm4(uint32_t* r, uint32_t addr) {
    asm volatile("ldmatrix.sync.aligned.m8n8.x4.shared.b16 {%0,%1,%2,%3}, [%4];"
        : "=r"(r[0]), "=r"(r[1]), "=r"(r[2]), "=r"(r[3]) : "r"(addr));
}

// fp16 warp MMA m16n8k16, fp32 accum (sm_80+ baseline PTX).
static __device__ __forceinline__ void mma16816(float* c,
        const uint32_t* a, uint32_t b0, uint32_t b1) {
    asm volatile(
        "mma.sync.aligned.m16n8k16.row.col.f32.f16.f16.f32 "
        "{%0,%1,%2,%3}, {%4,%5,%6,%7}, {%8,%9}, {%0,%1,%2,%3};"
        : "+f"(c[0]), "+f"(c[1]), "+f"(c[2]), "+f"(c[3])
        : "r"(a[0]), "r"(a[1]), "r"(a[2]), "r"(a[3]), "r"(b0), "r"(b1));
}

// ---------------------------------------------------------------------------
// Kernel 1: PERSISTENT tensor-core node GEMM, 2-term fp16 split:
//   D = Ah*Bh + Ah*Bl   (A fp16-hi only; B = Wcat^T in fp16 hi + lo residual)
// Calibrated error model: missing Al*B term ~2^-11 -> rel_err ~1.6e-4 (<1e-3).
// 8 warps (4M x 2N), warp tile 32x64; K=256 as 4 chunks of 64,
// double-buffered A; every chunk stages the NEXT chunk (cyclic across tiles)
// so ldg latency is always hidden by MMAs/epilogue.
// ---------------------------------------------------------------------------
__global__ __launch_bounds__(256, 1)
void node_gemm_mma(const float4* __restrict__ h4, const float* __restrict__ W1,
                   const float* __restrict__ b1, int n_nodes, int n_tiles)
{
    extern __shared__ char smem[];
    const uint32_t sb = smem_u32(smem);
    float* b1s = (float*)(smem + SM_B1);

    const int tid  = threadIdx.x;
    const int wid  = tid >> 5, lane = tid & 31;
    const int gid  = lane >> 2, tig = lane & 3;
    const int wm   = wid >> 1, wn = wid & 1;

    // Build B images once: B[n][k] = Wcat[k][n], fp16 hi + fp32-residual lo.
    {
        unsigned short* BH = (unsigned short*)(smem + SM_BH);
        unsigned short* BL = (unsigned short*)(smem + SM_BL);
        #pragma unroll 8
        for (int i = tid; i < 32768; i += 256) {
            int n = i & 127, k = i >> 7;
            float x = (n < 64) ? W1[k * 64 + n] : W1[(256 + k) * 64 + (n - 64)];
            __half hb = __float2half_rn(x);
            __half lb = __float2half_rn(x - __half2float(hb));
            BH[n * BP + k] = __half_as_ushort(hb);
            BL[n * BP + k] = __half_as_ushort(lb);
        }
    }
    if (tid < 64) b1s[tid] = b1[tid];

    // ldmatrix lane addressing.
    const int r8 = lane & 7;
    const uint32_t a_off = (uint32_t)((wm * 32 + (((lane >> 3) & 1) << 3) + r8) * APB
                                      + (((lane >> 4) & 1) << 4));
    const uint32_t b_row = (uint32_t)(wn * 64 + ((lane >> 4) << 3) + r8);
    const uint32_t b_off = b_row * (BP * 2) + (((lane >> 3) & 1) << 4);
    const uint32_t baseBH = sb + SM_BH + b_off;
    const uint32_t baseBL = sb + SM_BL + b_off;
    const uint32_t abuf[2] = { sb + SM_A0 + a_off, sb + SM_A1 + a_off };

    // Staging map: fixed float4 column per thread, 8 rows spaced 16.
    const int s_f4   = tid & 15;
    const int s_row0 = tid >> 4;

    // Prologue: stage first tile's chunk 0 into buf0.
    if (blockIdx.x < n_tiles) {
        const int node0 = blockIdx.x * 128;
        #pragma unroll
        for (int j = 0; j < 8; j++) {
            int row = s_row0 + j * 16;
            int node = node0 + row;
            float4 v = make_float4(0.f, 0.f, 0.f, 0.f);
            if (node < n_nodes) v = h4[(size_t)node * 64 + s_f4];
            __half2 p0 = __floats2half2_rn(v.x, v.y);
            __half2 p1 = __floats2half2_rn(v.z, v.w);
            *(uint2*)(smem + SM_A0 + row * APB + s_f4 * 8) =
                make_uint2(*(uint32_t*)&p0, *(uint32_t*)&p1);
        }
    }
    __syncthreads();   // also orders the one-time B build

    for (int tile = blockIdx.x; tile < n_tiles; tile += gridDim.x) {
        const int node0 = tile * 128;

        float c[2][8][4];
        #pragma unroll
        for (int mm = 0; mm < 2; mm++)
            #pragma unroll
            for (int nn = 0; nn < 8; nn++)
                #pragma unroll
                for (int q = 0; q < 4; q++) c[mm][nn][q] = 0.f;

        #pragma unroll
        for (int chunk = 0; chunk < 4; chunk++) {
            const int buf = chunk & 1;

            // Prefetch target: next chunk, or next tile's chunk 0.
            int pnode0 = node0, pchunk = chunk + 1;
            bool havepf = true;
            if (chunk == 3) {
                int nt = tile + gridDim.x;
                havepf = nt < n_tiles;
                pnode0 = nt * 128;
                pchunk = 0;
            }
            float4 pf[8];
            if (havepf) {
                #pragma unroll
                for (int j = 0; j < 8; j++) {
                    int node = pnode0 + s_row0 + j * 16;
                    pf[j] = make_float4(0.f, 0.f, 0.f, 0.f);
                    if (node < n_nodes)
                        pf[j] = h4[(size_t)node * 64 + pchunk * 16 + s_f4];
                }
            }

            // MMA over this chunk (4 k16-steps), 2 terms: Ah*Bh + Ah*Bl.
            #pragma unroll
            for (int ks = 0; ks < 4; ks++) {
                const uint32_t akb = (uint32_t)(ks * 32);
                const uint32_t bkb = (uint32_t)(chunk * 128 + ks * 32);

                uint32_t ah[2][4], bh[4][4], bl[4][4];
                ldsm4(ah[0], abuf[buf] + akb);
                ldsm4(ah[1], abuf[buf] + 16 * APB + akb);
                #pragma unroll
                for (int p = 0; p < 4; p++) {
                    ldsm4(bh[p], baseBH + (uint32_t)(p * 16 * BP * 2) + bkb);
                    ldsm4(bl[p], baseBL + (uint32_t)(p * 16 * BP * 2) + bkb);
                }

                #pragma unroll
                for (int mm = 0; mm < 2; mm++)
                    #pragma unroll
                    for (int nn = 0; nn < 8; nn++)
                        mma16816(c[mm][nn], ah[mm], bh[nn >> 1][(nn & 1) * 2],
                                 bh[nn >> 1][(nn & 1) * 2 + 1]);
                #pragma unroll
                for (int mm = 0; mm < 2; mm++)
                    #pragma unroll
                    for (int nn = 0; nn < 8; nn++)
                        mma16816(c[mm][nn], ah[mm], bl[nn >> 1][(nn & 1) * 2],
                                 bl[nn >> 1][(nn & 1) * 2 + 1]);
            }

            // Store prefetched chunk into the other buffer.
            if (havepf) {
                const int dst = SM_A0 + (1 - buf) * (SM_A1 - SM_A0);
                #pragma unroll
                for (int j = 0; j < 8; j++) {
                    int row = s_row0 + j * 16;
                    __half2 p0 = __floats2half2_rn(pf[j].x, pf[j].y);
                    __half2 p1 = __floats2half2_rn(pf[j].z, pf[j].w);
                    *(uint2*)(smem + dst + row * APB + s_f4 * 8) =
                        make_uint2(*(uint32_t*)&p0, *(uint32_t*)&p1);
                }
                __syncthreads();
            }
        }

        // Epilogue: fold b1 into cols<64 (warps with wn==0), write g_AB rows.
        // Overlaps the already-issued next-tile chunk-0 latency chain.
        #pragma unroll
        for (int mm = 0; mm < 2; mm++) {
            #pragma unroll
            for (int nn = 0; nn < 8; nn++) {
                int col = wn * 64 + nn * 8 + tig * 2;
                float bx = 0.f, by = 0.f;
                if (wn == 0) { bx = b1s[col]; by = b1s[col + 1]; }
                int na = node0 + wm * 32 + mm * 16 + gid;
                if (na < n_nodes)
                    *(float2*)&g_AB[(size_t)na * 128 + col] =
                        make_float2(c[mm][nn][0] + bx, c[mm][nn][1] + by);
                int nb = na + 8;
                if (nb < n_nodes)
                    *(float2*)&g_AB[(size_t)nb * 128 + col] =
                        make_float2(c[mm][nn][2] + bx, c[mm][nn][3] + by);
            }
        }
    }
}

// ---------------------------------------------------------------------------
// Kernel 2: per-edge epilogue. 8-lane groups: lane sub=lane&7 owns 8 hidden
// channels (2x float4 per side); 4 edges per warp-row, 2 rows = 8 edges/warp.
// Per 8 edges: 8 float4 loads + 6 shfls (vs 16 float2 + 40 shfls before).
// out[e] = sum_j relu(A[u][j] + B[v][j]) * W2[j] + b2.
// ---------------------------------------------------------------------------
__global__ __launch_bounds__(256)
void edge_kernel(const int* __restrict__ ei, const float* __restrict__ W2,
                 const float* __restrict__ b2, float* __restrict__ out, int n_edges)
{
    const int lane = threadIdx.x & 31;
    const int sub  = lane & 7;          // channel group within edge
    const int eg   = lane >> 3;         // 0..3: edge within warp-row
    const int w = (blockIdx.x * blockDim.x + threadIdx.x) >> 5;
    const int e0 = w * 8;
    if (e0 >= n_edges) return;

    const float4 w2a = *(const float4*)&W2[sub * 8];
    const float4 w2b = *(const float4*)&W2[sub * 8 + 4];
    const float bias = b2[0];

    int eidx[2];
    float4 a0[2], a1[2], b0[2], b1[2];
    #pragma unroll
    for (int r = 0; r < 2; r++) {
        int e = e0 + r * 4 + eg;
        if (e > n_edges - 1) e = n_edges - 1;   // clamp keeps loads batched
        eidx[r] = e;
        int u = ei[e];
        int v = ei[n_edges + e];
        const float4* pa = (const float4*)&g_AB[(size_t)u * 128 + sub * 8];
        const float4* pb = (const float4*)&g_AB[(size_t)v * 128 + 64 + sub * 8];
        a0[r] = pa[0]; a1[r] = pa[1];
        b0[r] = pb[0]; b1[r] = pb[1];
    }
    #pragma unroll
    for (int r = 0; r < 2; r++) {
        float p;
        p  = fmaxf(a0[r].x + b0[r].x, 0.f) * w2a.x;
        p  = fmaf(fmaxf(a0[r].y + b0[r].y, 0.f), w2a.y, p);
        p  = fmaf(fmaxf(a0[r].z + b0[r].z, 0.f), w2a.z, p);
        p  = fmaf(fmaxf(a0[r].w + b0[r].w, 0.f), w2a.w, p);
        p  = fmaf(fmaxf(a1[r].x + b1[r].x, 0.f), w2b.x, p);
        p  = fmaf(fmaxf(a1[r].y + b1[r].y, 0.f), w2b.y, p);
        p  = fmaf(fmaxf(a1[r].z + b1[r].z, 0.f), w2b.z, p);
        p  = fmaf(fmaxf(a1[r].w + b1[r].w, 0.f), w2b.w, p);
        p += __shfl_xor_sync(0xffffffffu, p, 1);
        p += __shfl_xor_sync(0xffffffffu, p, 2);
        p += __shfl_xor_sync(0xffffffffu, p, 4);
        if (sub == 0 && e0 + r * 4 + eg < n_edges) out[eidx[r]] = p + bias;
    }
}

// ---------------------------------------------------------------------------
// Launch. Inputs (metadata order): h, edge_index (int32), W1, b1, W2, b2.
// ---------------------------------------------------------------------------
extern "C" void kernel_launch(void* const* d_in, const int* in_sizes, int n_in,
                              void* d_out, int out_size)
{
    const float* h   = (const float*)d_in[0];
    const int*   ei  = (const int*)d_in[1];
    const float* W1  = (const float*)d_in[2];
    const float* b1  = (const float*)d_in[3];
    const float* W2  = (const float*)d_in[4];
    const float* b2  = (const float*)d_in[5];
    float*       out = (float*)d_out;

    const int n_nodes = in_sizes[0] / IN_FEATS;   // 100000
    const int n_edges = out_size;                 // 500000
    const int n_tiles = (n_nodes + 127) / 128;    // 782

    cudaFuncSetAttribute(node_gemm_mma,
                         cudaFuncAttributeMaxDynamicSharedMemorySize, SMEM_TOTAL);
    int gemm_blocks = n_tiles < NSM ? n_tiles : NSM;
    node_gemm_mma<<<gemm_blocks, 256, SMEM_TOTAL>>>((const float4*)h, W1, b1,
                                                    n_nodes, n_tiles);

    int edge_blocks = (n_edges + 63) / 64;        // 64 edges per 256-thread block
    edge_kernel<<<edge_blocks, 256>>>(ei, W2, b2, out, n_edges);
}

// round 13
// speedup vs baseline: 5.3145x; 1.0532x over previous
#include <cuda_runtime.h>
#include <cuda_fp16.h>
#include <cstdint>

// Problem constants
#define N_NODES  100000
#define N_EDGES  500000
#define IN_FEATS 256
#define HIDDEN   64
#define NSM      148

// Fused per-node activations in fp16:
//   g_AB2[node][0..31]  = half2 pairs of A = h@W1_top + b1   (cols 0..63)
//   g_AB2[node][32..63] = half2 pairs of B = h@W1_bot        (cols 64..127)
// One 128 B L1 line per half per node -> minimal gather wavefronts.
__device__ __half2 g_AB2[(size_t)N_NODES * 64];

#define BP   264        // B pitch in fp16 (row = 528 B; 132 words % 32 == 4 -> LDSM conflict-free)
#define APB  144        // A pitch in bytes (72 fp16; 36 words % 32 == 4 -> LDSM conflict-free)

// smem byte offsets: B hi | B lo | A buf0 | A buf1 | b1
#define SM_BH   0
#define SM_BL   67584
#define SM_A0   135168
#define SM_A1   153600
#define SM_B1   172032
#define SMEM_TOTAL 172288

static __device__ __forceinline__ uint32_t smem_u32(const void* p) {
    uint32_t a;
    asm("{ .reg .u64 t; cvta.to.shared.u64 t, %1; cvt.u32.u64 %0, t; }" : "=r"(a) : "l"(p));
    return a;
}

static __device__ __forceinline__ void ldsm4(uint32_t* r, uint32_t addr) {
    asm volatile("ldmatrix.sync.aligned.m8n8.x4.shared.b16 {%0,%1,%2,%3}, [%4];"
        : "=r"(r[0]), "=r"(r[1]), "=r"(r[2]), "=r"(r[3]) : "r"(addr));
}

// fp16 warp MMA m16n8k16, fp32 accum (sm_80+ baseline PTX).
static __device__ __forceinline__ void mma16816(float* c,
        const uint32_t* a, uint32_t b0, uint32_t b1) {
    asm volatile(
        "mma.sync.aligned.m16n8k16.row.col.f32.f16.f16.f32 "
        "{%0,%1,%2,%3}, {%4,%5,%6,%7}, {%8,%9}, {%0,%1,%2,%3};"
        : "+f"(c[0]), "+f"(c[1]), "+f"(c[2]), "+f"(c[3])
        : "r"(a[0]), "r"(a[1]), "r"(a[2]), "r"(a[3]), "r"(b0), "r"(b1));
}

// ---------------------------------------------------------------------------
// Kernel 1: PERSISTENT tensor-core node GEMM, 2-term fp16 split:
//   D = Ah*Bh + Ah*Bl   (A fp16-hi only; B = Wcat^T in fp16 hi + lo residual)
// 8 warps (4M x 2N), warp tile 32x64; K=256 as 4 chunks of 64,
// double-buffered A; every chunk stages the NEXT chunk (cyclic across tiles).
// Epilogue converts fp32 accums to half2 and writes g_AB2.
// ---------------------------------------------------------------------------
__global__ __launch_bounds__(256, 1)
void node_gemm_mma(const float4* __restrict__ h4, const float* __restrict__ W1,
                   const float* __restrict__ b1, int n_nodes, int n_tiles)
{
    extern __shared__ char smem[];
    const uint32_t sb = smem_u32(smem);
    float* b1s = (float*)(smem + SM_B1);

    const int tid  = threadIdx.x;
    const int wid  = tid >> 5, lane = tid & 31;
    const int gid  = lane >> 2, tig = lane & 3;
    const int wm   = wid >> 1, wn = wid & 1;

    // Build B images once: B[n][k] = Wcat[k][n], fp16 hi + fp32-residual lo.
    {
        unsigned short* BH = (unsigned short*)(smem + SM_BH);
        unsigned short* BL = (unsigned short*)(smem + SM_BL);
        #pragma unroll 8
        for (int i = tid; i < 32768; i += 256) {
            int n = i & 127, k = i >> 7;
            float x = (n < 64) ? W1[k * 64 + n] : W1[(256 + k) * 64 + (n - 64)];
            __half hb = __float2half_rn(x);
            __half lb = __float2half_rn(x - __half2float(hb));
            BH[n * BP + k] = __half_as_ushort(hb);
            BL[n * BP + k] = __half_as_ushort(lb);
        }
    }
    if (tid < 64) b1s[tid] = b1[tid];

    // ldmatrix lane addressing.
    const int r8 = lane & 7;
    const uint32_t a_off = (uint32_t)((wm * 32 + (((lane >> 3) & 1) << 3) + r8) * APB
                                      + (((lane >> 4) & 1) << 4));
    const uint32_t b_row = (uint32_t)(wn * 64 + ((lane >> 4) << 3) + r8);
    const uint32_t b_off = b_row * (BP * 2) + (((lane >> 3) & 1) << 4);
    const uint32_t baseBH = sb + SM_BH + b_off;
    const uint32_t baseBL = sb + SM_BL + b_off;
    const uint32_t abuf[2] = { sb + SM_A0 + a_off, sb + SM_A1 + a_off };

    // Staging map: fixed float4 column per thread, 8 rows spaced 16.
    const int s_f4   = tid & 15;
    const int s_row0 = tid >> 4;

    // Prologue: stage first tile's chunk 0 into buf0.
    if (blockIdx.x < n_tiles) {
        const int node0 = blockIdx.x * 128;
        #pragma unroll
        for (int j = 0; j < 8; j++) {
            int row = s_row0 + j * 16;
            int node = node0 + row;
            float4 v = make_float4(0.f, 0.f, 0.f, 0.f);
            if (node < n_nodes) v = h4[(size_t)node * 64 + s_f4];
            __half2 p0 = __floats2half2_rn(v.x, v.y);
            __half2 p1 = __floats2half2_rn(v.z, v.w);
            *(uint2*)(smem + SM_A0 + row * APB + s_f4 * 8) =
                make_uint2(*(uint32_t*)&p0, *(uint32_t*)&p1);
        }
    }
    __syncthreads();   // also orders the one-time B build

    for (int tile = blockIdx.x; tile < n_tiles; tile += gridDim.x) {
        const int node0 = tile * 128;

        float c[2][8][4];
        #pragma unroll
        for (int mm = 0; mm < 2; mm++)
            #pragma unroll
            for (int nn = 0; nn < 8; nn++)
                #pragma unroll
                for (int q = 0; q < 4; q++) c[mm][nn][q] = 0.f;

        #pragma unroll
        for (int chunk = 0; chunk < 4; chunk++) {
            const int buf = chunk & 1;

            // Prefetch target: next chunk, or next tile's chunk 0.
            int pnode0 = node0, pchunk = chunk + 1;
            bool havepf = true;
            if (chunk == 3) {
                int nt = tile + gridDim.x;
                havepf = nt < n_tiles;
                pnode0 = nt * 128;
                pchunk = 0;
            }
            float4 pf[8];
            if (havepf) {
                #pragma unroll
                for (int j = 0; j < 8; j++) {
                    int node = pnode0 + s_row0 + j * 16;
                    pf[j] = make_float4(0.f, 0.f, 0.f, 0.f);
                    if (node < n_nodes)
                        pf[j] = h4[(size_t)node * 64 + pchunk * 16 + s_f4];
                }
            }

            // MMA over this chunk (4 k16-steps), 2 terms: Ah*Bh + Ah*Bl.
            #pragma unroll
            for (int ks = 0; ks < 4; ks++) {
                const uint32_t akb = (uint32_t)(ks * 32);
                const uint32_t bkb = (uint32_t)(chunk * 128 + ks * 32);

                uint32_t ah[2][4], bh[4][4], bl[4][4];
                ldsm4(ah[0], abuf[buf] + akb);
                ldsm4(ah[1], abuf[buf] + 16 * APB + akb);
                #pragma unroll
                for (int p = 0; p < 4; p++) {
                    ldsm4(bh[p], baseBH + (uint32_t)(p * 16 * BP * 2) + bkb);
                    ldsm4(bl[p], baseBL + (uint32_t)(p * 16 * BP * 2) + bkb);
                }

                #pragma unroll
                for (int mm = 0; mm < 2; mm++)
                    #pragma unroll
                    for (int nn = 0; nn < 8; nn++)
                        mma16816(c[mm][nn], ah[mm], bh[nn >> 1][(nn & 1) * 2],
                                 bh[nn >> 1][(nn & 1) * 2 + 1]);
                #pragma unroll
                for (int mm = 0; mm < 2; mm++)
                    #pragma unroll
                    for (int nn = 0; nn < 8; nn++)
                        mma16816(c[mm][nn], ah[mm], bl[nn >> 1][(nn & 1) * 2],
                                 bl[nn >> 1][(nn & 1) * 2 + 1]);
            }

            // Store prefetched chunk into the other buffer.
            if (havepf) {
                const int dst = SM_A0 + (1 - buf) * (SM_A1 - SM_A0);
                #pragma unroll
                for (int j = 0; j < 8; j++) {
                    int row = s_row0 + j * 16;
                    __half2 p0 = __floats2half2_rn(pf[j].x, pf[j].y);
                    __half2 p1 = __floats2half2_rn(pf[j].z, pf[j].w);
                    *(uint2*)(smem + dst + row * APB + s_f4 * 8) =
                        make_uint2(*(uint32_t*)&p0, *(uint32_t*)&p1);
                }
                __syncthreads();
            }
        }

        // Epilogue: fold b1 into cols<64 (warps with wn==0), convert to half2,
        // write g_AB2 rows. Overlaps next-tile chunk-0 ldg latency.
        #pragma unroll
        for (int mm = 0; mm < 2; mm++) {
            #pragma unroll
            for (int nn = 0; nn < 8; nn++) {
                int col = wn * 64 + nn * 8 + tig * 2;
                float bx = 0.f, by = 0.f;
                if (wn == 0) { bx = b1s[col]; by = b1s[col + 1]; }
                int h2i = col >> 1;                 // half2 index within row
                int na = node0 + wm * 32 + mm * 16 + gid;
                if (na < n_nodes)
                    g_AB2[(size_t)na * 64 + h2i] =
                        __floats2half2_rn(c[mm][nn][0] + bx, c[mm][nn][1] + by);
                int nb = na + 8;
                if (nb < n_nodes)
                    g_AB2[(size_t)nb * 64 + h2i] =
                        __floats2half2_rn(c[mm][nn][2] + bx, c[mm][nn][3] + by);
            }
        }
    }
}

// ---------------------------------------------------------------------------
// Kernel 2: per-edge epilogue over fp16 activations. Lane sub=lane&7 owns 8
// hidden channels via ONE uint4 (8 halves) per side; 4 edges per warp-row,
// 2 rows = 8 edges/warp. Per edge-side: 8 lanes x 16 B = one 128 B line.
// out[e] = sum_j relu(A[u][j] + B[v][j]) * W2[j] + b2   (fp32 accumulate)
// ---------------------------------------------------------------------------
__global__ __launch_bounds__(256)
void edge_kernel(const int* __restrict__ ei, const float* __restrict__ W2,
                 const float* __restrict__ b2, float* __restrict__ out, int n_edges)
{
    const int lane = threadIdx.x & 31;
    const int sub  = lane & 7;          // channel group within edge
    const int eg   = lane >> 3;         // 0..3: edge within warp-row
    const int w = (blockIdx.x * blockDim.x + threadIdx.x) >> 5;
    const int e0 = w * 8;
    if (e0 >= n_edges) return;

    const float4 w2a = *(const float4*)&W2[sub * 8];
    const float4 w2b = *(const float4*)&W2[sub * 8 + 4];
    const float bias = b2[0];

    int eidx[2];
    uint4 av[2], bv[2];
    #pragma unroll
    for (int r = 0; r < 2; r++) {
        int e = e0 + r * 4 + eg;
        if (e > n_edges - 1) e = n_edges - 1;   // clamp keeps loads batched
        eidx[r] = e;
        int u = ei[e];
        int v = ei[n_edges + e];
        av[r] = *(const uint4*)&g_AB2[(size_t)u * 64 + sub * 4];
        bv[r] = *(const uint4*)&g_AB2[(size_t)v * 64 + 32 + sub * 4];
    }
    #pragma unroll
    for (int r = 0; r < 2; r++) {
        const __half2* ah = (const __half2*)&av[r];
        const __half2* bh = (const __half2*)&bv[r];
        float2 s0 = __half22float2(__hadd2(ah[0], bh[0]));
        float2 s1 = __half22float2(__hadd2(ah[1], bh[1]));
        float2 s2 = __half22float2(__hadd2(ah[2], bh[2]));
        float2 s3 = __half22float2(__hadd2(ah[3], bh[3]));
        float p;
        p  = fmaxf(s0.x, 0.f) * w2a.x;
        p  = fmaf(fmaxf(s0.y, 0.f), w2a.y, p);
        p  = fmaf(fmaxf(s1.x, 0.f), w2a.z, p);
        p  = fmaf(fmaxf(s1.y, 0.f), w2a.w, p);
        p  = fmaf(fmaxf(s2.x, 0.f), w2b.x, p);
        p  = fmaf(fmaxf(s2.y, 0.f), w2b.y, p);
        p  = fmaf(fmaxf(s3.x, 0.f), w2b.z, p);
        p  = fmaf(fmaxf(s3.y, 0.f), w2b.w, p);
        p += __shfl_xor_sync(0xffffffffu, p, 1);
        p += __shfl_xor_sync(0xffffffffu, p, 2);
        p += __shfl_xor_sync(0xffffffffu, p, 4);
        if (sub == 0 && e0 + r * 4 + eg < n_edges) out[eidx[r]] = p + bias;
    }
}

// ---------------------------------------------------------------------------
// Launch. Inputs (metadata order): h, edge_index (int32), W1, b1, W2, b2.
// ---------------------------------------------------------------------------
extern "C" void kernel_launch(void* const* d_in, const int* in_sizes, int n_in,
                              void* d_out, int out_size)
{
    const float* h   = (const float*)d_in[0];
    const int*   ei  = (const int*)d_in[1];
    const float* W1  = (const float*)d_in[2];
    const float* b1  = (const float*)d_in[3];
    const float* W2  = (const float*)d_in[4];
    const float* b2  = (const float*)d_in[5];
    float*       out = (float*)d_out;

    const int n_nodes = in_sizes[0] / IN_FEATS;   // 100000
    const int n_edges = out_size;                 // 500000
    const int n_tiles = (n_nodes + 127) / 128;    // 782

    cudaFuncSetAttribute(node_gemm_mma,
                         cudaFuncAttributeMaxDynamicSharedMemorySize, SMEM_TOTAL);
    int gemm_blocks = n_tiles < NSM ? n_tiles : NSM;
    node_gemm_mma<<<gemm_blocks, 256, SMEM_TOTAL>>>((const float4*)h, W1, b1,
                                                    n_nodes, n_tiles);

    int edge_blocks = (n_edges + 63) / 64;        // 64 edges per 256-thread block
    edge_kernel<<<edge_blocks, 256>>>(ei, W2, b2, out, n_edges);
}

// round 14
// speedup vs baseline: 6.0894x; 1.1458x over previous
#include <cuda_runtime.h>
#include <cuda_fp16.h>
#include <cstdint>

// Problem constants
#define N_NODES  100000
#define N_EDGES  500000
#define IN_FEATS 256
#define HIDDEN   64
#define NSM      148

// Fused per-node activations in fp16:
//   g_AB2[node][0..31]  = half2 pairs of A = h@W1_top + b1   (cols 0..63)
//   g_AB2[node][32..63] = half2 pairs of B = h@W1_bot        (cols 64..127)
__device__ __half2 g_AB2[(size_t)N_NODES * 64];

#define BP   264        // B pitch in fp16 (row = 528 B; 132 words % 32 == 4 -> LDSM conflict-free)
#define APB  144        // A pitch in bytes (72 fp16; 36 words % 32 == 4 -> LDSM conflict-free)

// smem byte offsets: B hi | A buf0 | A buf1 | b1   (B-lo dropped -> 2 CTAs/SM)
#define SM_BH   0
#define SM_A0   67584
#define SM_A1   86016
#define SM_B1   104448
#define SMEM_TOTAL 104704

static __device__ __forceinline__ uint32_t smem_u32(const void* p) {
    uint32_t a;
    asm("{ .reg .u64 t; cvta.to.shared.u64 t, %1; cvt.u32.u64 %0, t; }" : "=r"(a) : "l"(p));
    return a;
}

static __device__ __forceinline__ void ldsm4(uint32_t* r, uint32_t addr) {
    asm volatile("ldmatrix.sync.aligned.m8n8.x4.shared.b16 {%0,%1,%2,%3}, [%4];"
        : "=r"(r[0]), "=r"(r[1]), "=r"(r[2]), "=r"(r[3]) : "r"(addr));
}

// fp16 warp MMA m16n8k16, fp32 accum (sm_80+ baseline PTX).
static __device__ __forceinline__ void mma16816(float* c,
        const uint32_t* a, uint32_t b0, uint32_t b1) {
    asm volatile(
        "mma.sync.aligned.m16n8k16.row.col.f32.f16.f16.f32 "
        "{%0,%1,%2,%3}, {%4,%5,%6,%7}, {%8,%9}, {%0,%1,%2,%3};"
        : "+f"(c[0]), "+f"(c[1]), "+f"(c[2]), "+f"(c[3])
        : "r"(a[0]), "r"(a[1]), "r"(a[2]), "r"(a[3]), "r"(b0), "r"(b1));
}

// ---------------------------------------------------------------------------
// Kernel 1: PERSISTENT tensor-core node GEMM, plain fp16: D = Ah*Bh.
// Calibrated error model: four incoherent 2^-11 sources -> rel_err ~4.7e-4.
// 8 warps (4M x 2N), warp tile 32x64; K=256 as 4 chunks of 64,
// double-buffered A; every chunk stages the NEXT chunk (cyclic across tiles).
// 102 KB smem -> 2 CTAs/SM (4 warps/SMSP latency hiding + cross-CTA overlap).
// ---------------------------------------------------------------------------
__global__ __launch_bounds__(256, 2)
void node_gemm_mma(const float4* __restrict__ h4, const float* __restrict__ W1,
                   const float* __restrict__ b1, int n_nodes, int n_tiles)
{
    extern __shared__ char smem[];
    const uint32_t sb = smem_u32(smem);
    float* b1s = (float*)(smem + SM_B1);

    const int tid  = threadIdx.x;
    const int wid  = tid >> 5, lane = tid & 31;
    const int gid  = lane >> 2, tig = lane & 3;
    const int wm   = wid >> 1, wn = wid & 1;

    // Build B image once: B[n][k] = Wcat[k][n] in fp16.
    {
        unsigned short* BH = (unsigned short*)(smem + SM_BH);
        #pragma unroll 8
        for (int i = tid; i < 32768; i += 256) {
            int n = i & 127, k = i >> 7;
            float x = (n < 64) ? W1[k * 64 + n] : W1[(256 + k) * 64 + (n - 64)];
            BH[n * BP + k] = __half_as_ushort(__float2half_rn(x));
        }
    }
    if (tid < 64) b1s[tid] = b1[tid];

    // ldmatrix lane addressing.
    const int r8 = lane & 7;
    const uint32_t a_off = (uint32_t)((wm * 32 + (((lane >> 3) & 1) << 3) + r8) * APB
                                      + (((lane >> 4) & 1) << 4));
    const uint32_t b_row = (uint32_t)(wn * 64 + ((lane >> 4) << 3) + r8);
    const uint32_t b_off = b_row * (BP * 2) + (((lane >> 3) & 1) << 4);
    const uint32_t baseBH = sb + SM_BH + b_off;
    const uint32_t abuf[2] = { sb + SM_A0 + a_off, sb + SM_A1 + a_off };

    // Staging map: fixed float4 column per thread, 8 rows spaced 16.
    const int s_f4   = tid & 15;
    const int s_row0 = tid >> 4;

    // Prologue: stage first tile's chunk 0 into buf0.
    if (blockIdx.x < n_tiles) {
        const int node0 = blockIdx.x * 128;
        #pragma unroll
        for (int j = 0; j < 8; j++) {
            int row = s_row0 + j * 16;
            int node = node0 + row;
            float4 v = make_float4(0.f, 0.f, 0.f, 0.f);
            if (node < n_nodes) v = h4[(size_t)node * 64 + s_f4];
            __half2 p0 = __floats2half2_rn(v.x, v.y);
            __half2 p1 = __floats2half2_rn(v.z, v.w);
            *(uint2*)(smem + SM_A0 + row * APB + s_f4 * 8) =
                make_uint2(*(uint32_t*)&p0, *(uint32_t*)&p1);
        }
    }
    __syncthreads();   // also orders the one-time B build

    for (int tile = blockIdx.x; tile < n_tiles; tile += gridDim.x) {
        const int node0 = tile * 128;

        float c[2][8][4];
        #pragma unroll
        for (int mm = 0; mm < 2; mm++)
            #pragma unroll
            for (int nn = 0; nn < 8; nn++)
                #pragma unroll
                for (int q = 0; q < 4; q++) c[mm][nn][q] = 0.f;

        #pragma unroll
        for (int chunk = 0; chunk < 4; chunk++) {
            const int buf = chunk & 1;

            // Prefetch target: next chunk, or next tile's chunk 0.
            int pnode0 = node0, pchunk = chunk + 1;
            bool havepf = true;
            if (chunk == 3) {
                int nt = tile + gridDim.x;
                havepf = nt < n_tiles;
                pnode0 = nt * 128;
                pchunk = 0;
            }
            float4 pf[8];
            if (havepf) {
                #pragma unroll
                for (int j = 0; j < 8; j++) {
                    int node = pnode0 + s_row0 + j * 16;
                    pf[j] = make_float4(0.f, 0.f, 0.f, 0.f);
                    if (node < n_nodes)
                        pf[j] = h4[(size_t)node * 64 + pchunk * 16 + s_f4];
                }
            }

            // MMA over this chunk (4 k16-steps), single term Ah*Bh.
            #pragma unroll
            for (int ks = 0; ks < 4; ks++) {
                const uint32_t akb = (uint32_t)(ks * 32);
                const uint32_t bkb = (uint32_t)(chunk * 128 + ks * 32);

                uint32_t ah[2][4], bh[4][4];
                ldsm4(ah[0], abuf[buf] + akb);
                ldsm4(ah[1], abuf[buf] + 16 * APB + akb);
                #pragma unroll
                for (int p = 0; p < 4; p++)
                    ldsm4(bh[p], baseBH + (uint32_t)(p * 16 * BP * 2) + bkb);

                #pragma unroll
                for (int mm = 0; mm < 2; mm++)
                    #pragma unroll
                    for (int nn = 0; nn < 8; nn++)
                        mma16816(c[mm][nn], ah[mm], bh[nn >> 1][(nn & 1) * 2],
                                 bh[nn >> 1][(nn & 1) * 2 + 1]);
            }

            // Store prefetched chunk into the other buffer.
            if (havepf) {
                const int dst = SM_A0 + (1 - buf) * (SM_A1 - SM_A0);
                #pragma unroll
                for (int j = 0; j < 8; j++) {
                    int row = s_row0 + j * 16;
                    __half2 p0 = __floats2half2_rn(pf[j].x, pf[j].y);
                    __half2 p1 = __floats2half2_rn(pf[j].z, pf[j].w);
                    *(uint2*)(smem + dst + row * APB + s_f4 * 8) =
                        make_uint2(*(uint32_t*)&p0, *(uint32_t*)&p1);
                }
                __syncthreads();
            }
        }

        // Epilogue: fold b1 into cols<64 (warps with wn==0), convert to half2,
        // write g_AB2 rows. Overlaps next-tile chunk-0 ldg latency.
        #pragma unroll
        for (int mm = 0; mm < 2; mm++) {
            #pragma unroll
            for (int nn = 0; nn < 8; nn++) {
                int col = wn * 64 + nn * 8 + tig * 2;
                float bx = 0.f, by = 0.f;
                if (wn == 0) { bx = b1s[col]; by = b1s[col + 1]; }
                int h2i = col >> 1;                 // half2 index within row
                int na = node0 + wm * 32 + mm * 16 + gid;
                if (na < n_nodes)
                    g_AB2[(size_t)na * 64 + h2i] =
                        __floats2half2_rn(c[mm][nn][0] + bx, c[mm][nn][1] + by);
                int nb = na + 8;
                if (nb < n_nodes)
                    g_AB2[(size_t)nb * 64 + h2i] =
                        __floats2half2_rn(c[mm][nn][2] + bx, c[mm][nn][3] + by);
            }
        }
    }
}

// ---------------------------------------------------------------------------
// Kernel 2: per-edge epilogue over fp16 activations. Lane sub=lane&7 owns 8
// hidden channels via ONE uint4 (8 halves) per side; 4 edges per warp-row,
// 2 rows = 8 edges/warp. Per edge-side: 8 lanes x 16 B = one 128 B line.
// out[e] = sum_j relu(A[u][j] + B[v][j]) * W2[j] + b2   (fp32 accumulate)
// ---------------------------------------------------------------------------
__global__ __launch_bounds__(256)
void edge_kernel(const int* __restrict__ ei, const float* __restrict__ W2,
                 const float* __restrict__ b2, float* __restrict__ out, int n_edges)
{
    const int lane = threadIdx.x & 31;
    const int sub  = lane & 7;          // channel group within edge
    const int eg   = lane >> 3;         // 0..3: edge within warp-row
    const int w = (blockIdx.x * blockDim.x + threadIdx.x) >> 5;
    const int e0 = w * 8;
    if (e0 >= n_edges) return;

    const float4 w2a = *(const float4*)&W2[sub * 8];
    const float4 w2b = *(const float4*)&W2[sub * 8 + 4];
    const float bias = b2[0];

    int eidx[2];
    uint4 av[2], bv[2];
    #pragma unroll
    for (int r = 0; r < 2; r++) {
        int e = e0 + r * 4 + eg;
        if (e > n_edges - 1) e = n_edges - 1;   // clamp keeps loads batched
        eidx[r] = e;
        int u = ei[e];
        int v = ei[n_edges + e];
        av[r] = *(const uint4*)&g_AB2[(size_t)u * 64 + sub * 4];
        bv[r] = *(const uint4*)&g_AB2[(size_t)v * 64 + 32 + sub * 4];
    }
    #pragma unroll
    for (int r = 0; r < 2; r++) {
        const __half2* ah = (const __half2*)&av[r];
        const __half2* bh = (const __half2*)&bv[r];
        float2 s0 = __half22float2(__hadd2(ah[0], bh[0]));
        float2 s1 = __half22float2(__hadd2(ah[1], bh[1]));
        float2 s2 = __half22float2(__hadd2(ah[2], bh[2]));
        float2 s3 = __half22float2(__hadd2(ah[3], bh[3]));
        float p;
        p  = fmaxf(s0.x, 0.f) * w2a.x;
        p  = fmaf(fmaxf(s0.y, 0.f), w2a.y, p);
        p  = fmaf(fmaxf(s1.x, 0.f), w2a.z, p);
        p  = fmaf(fmaxf(s1.y, 0.f), w2a.w, p);
        p  = fmaf(fmaxf(s2.x, 0.f), w2b.x, p);
        p  = fmaf(fmaxf(s2.y, 0.f), w2b.y, p);
        p  = fmaf(fmaxf(s3.x, 0.f), w2b.z, p);
        p  = fmaf(fmaxf(s3.y, 0.f), w2b.w, p);
        p += __shfl_xor_sync(0xffffffffu, p, 1);
        p += __shfl_xor_sync(0xffffffffu, p, 2);
        p += __shfl_xor_sync(0xffffffffu, p, 4);
        if (sub == 0 && e0 + r * 4 + eg < n_edges) out[eidx[r]] = p + bias;
    }
}

// ---------------------------------------------------------------------------
// Launch. Inputs (metadata order): h, edge_index (int32), W1, b1, W2, b2.
// ---------------------------------------------------------------------------
extern "C" void kernel_launch(void* const* d_in, const int* in_sizes, int n_in,
                              void* d_out, int out_size)
{
    const float* h   = (const float*)d_in[0];
    const int*   ei  = (const int*)d_in[1];
    const float* W1  = (const float*)d_in[2];
    const float* b1  = (const float*)d_in[3];
    const float* W2  = (const float*)d_in[4];
    const float* b2  = (const float*)d_in[5];
    float*       out = (float*)d_out;

    const int n_nodes = in_sizes[0] / IN_FEATS;   // 100000
    const int n_edges = out_size;                 // 500000
    const int n_tiles = (n_nodes + 127) / 128;    // 782

    cudaFuncSetAttribute(node_gemm_mma,
                         cudaFuncAttributeMaxDynamicSharedMemorySize, SMEM_TOTAL);
    int max_blocks = 2 * NSM;                     // 2 CTAs/SM
    int gemm_blocks = n_tiles < max_blocks ? n_tiles : max_blocks;
    node_gemm_mma<<<gemm_blocks, 256, SMEM_TOTAL>>>((const float4*)h, W1, b1,
                                                    n_nodes, n_tiles);

    int edge_blocks = (n_edges + 63) / 64;        // 64 edges per 256-thread block
    edge_kernel<<<edge_blocks, 256>>>(ei, W2, b2, out, n_edges);
}

// round 15
// speedup vs baseline: 6.4408x; 1.0577x over previous
#include <cuda_runtime.h>
#include <cuda_fp16.h>
#include <cstdint>

// Problem constants
#define N_NODES  100000
#define N_EDGES  500000
#define IN_FEATS 256
#define HIDDEN   64
#define NSM      148

// Fused per-node activations in fp16:
//   g_AB2[node][0..31]  = half2 pairs of A = h@W1_top + b1   (cols 0..63)
//   g_AB2[node][32..63] = half2 pairs of B = h@W1_bot        (cols 64..127)
__device__ __half2 g_AB2[(size_t)N_NODES * 64];

#define BP   264        // B pitch in fp16 (row = 528 B; 132 words % 32 == 4 -> LDSM conflict-free)
#define APB  144        // A pitch in bytes (72 fp16; 36 words % 32 == 4 -> LDSM conflict-free)

// smem byte offsets: B hi | A buf0 | A buf1 | b1   (102 KB -> 2 CTAs/SM)
#define SM_BH   0
#define SM_A0   67584
#define SM_A1   86016
#define SM_B1   104448
#define SMEM_TOTAL 104704

static __device__ __forceinline__ uint32_t smem_u32(const void* p) {
    uint32_t a;
    asm("{ .reg .u64 t; cvta.to.shared.u64 t, %1; cvt.u32.u64 %0, t; }" : "=r"(a) : "l"(p));
    return a;
}

// Pair-scope named barrier: 2 warps (64 threads), id = pair+1 (0 reserved).
static __device__ __forceinline__ void bar_pair(int id) {
    asm volatile("bar.sync %0, %1;" :: "r"(id), "r"(64) : "memory");
}

static __device__ __forceinline__ void ldsm4(uint32_t* r, uint32_t addr) {
    asm volatile("ldmatrix.sync.aligned.m8n8.x4.shared.b16 {%0,%1,%2,%3}, [%4];"
        : "=r"(r[0]), "=r"(r[1]), "=r"(r[2]), "=r"(r[3]) : "r"(addr));
}

// fp16 warp MMA m16n8k16, fp32 accum (sm_80+ baseline PTX).
static __device__ __forceinline__ void mma16816(float* c,
        const uint32_t* a, uint32_t b0, uint32_t b1) {
    asm volatile(
        "mma.sync.aligned.m16n8k16.row.col.f32.f16.f16.f32 "
        "{%0,%1,%2,%3}, {%4,%5,%6,%7}, {%8,%9}, {%0,%1,%2,%3};"
        : "+f"(c[0]), "+f"(c[1]), "+f"(c[2]), "+f"(c[3])
        : "r"(a[0]), "r"(a[1]), "r"(a[2]), "r"(a[3]), "r"(b0), "r"(b1));
}

// ---------------------------------------------------------------------------
// Kernel 1: PERSISTENT tensor-core node GEMM, plain fp16: D = Ah*Bh.
// 8 warps (4M x 2N), warp tile 32x64; K=256 as 4 chunks of 64.
// A consumption is PAIR-LOCAL (warps sharing wm read only rows wm*32..+31),
// so A is staged per-pair and synchronized with bar.sync(wm+1, 64) — the
// 4 pairs (x2 CTAs/SM = 8 streams) decouple, removing CTA-wide sync convoys.
// Double-buffered A; every chunk stages the NEXT chunk (cyclic across tiles).
// ---------------------------------------------------------------------------
__global__ __launch_bounds__(256, 2)
void node_gemm_mma(const float4* __restrict__ h4, const float* __restrict__ W1,
                   const float* __restrict__ b1, int n_nodes, int n_tiles)
{
    extern __shared__ char smem[];
    const uint32_t sb = smem_u32(smem);
    float* b1s = (float*)(smem + SM_B1);

    const int tid  = threadIdx.x;
    const int wid  = tid >> 5, lane = tid & 31;
    const int gid  = lane >> 2, tig = lane & 3;
    const int wm   = wid >> 1, wn = wid & 1;
    const int bar_id = wm + 1;

    // Build B image once: B[n][k] = Wcat[k][n] in fp16.
    {
        unsigned short* BH = (unsigned short*)(smem + SM_BH);
        #pragma unroll 8
        for (int i = tid; i < 32768; i += 256) {
            int n = i & 127, k = i >> 7;
            float x = (n < 64) ? W1[k * 64 + n] : W1[(256 + k) * 64 + (n - 64)];
            BH[n * BP + k] = __half_as_ushort(__float2half_rn(x));
        }
    }
    if (tid < 64) b1s[tid] = b1[tid];
    __syncthreads();   // one-time: B + b1 visible to all warps

    // ldmatrix lane addressing.
    const int r8 = lane & 7;
    const uint32_t a_off = (uint32_t)((wm * 32 + (((lane >> 3) & 1) << 3) + r8) * APB
                                      + (((lane >> 4) & 1) << 4));
    const uint32_t b_row = (uint32_t)(wn * 64 + ((lane >> 4) << 3) + r8);
    const uint32_t b_off = b_row * (BP * 2) + (((lane >> 3) & 1) << 4);
    const uint32_t baseBH = sb + SM_BH + b_off;
    const uint32_t abuf[2] = { sb + SM_A0 + a_off, sb + SM_A1 + a_off };

    // Pair-local staging map: pair wm stages rows wm*32..wm*32+31.
    // 64 threads: fixed float4 column, 8 rows spaced 4.
    const int wtid   = tid & 63;
    const int s_f4   = wtid & 15;                 // k float4 index 0..15
    const int s_row0 = wm * 32 + (wtid >> 4);     // rows s_row0 + j*4, j=0..7

    // Prologue: stage first tile's chunk 0 into buf0 (pair-local rows).
    if (blockIdx.x < n_tiles) {
        const int node0 = blockIdx.x * 128;
        #pragma unroll
        for (int j = 0; j < 8; j++) {
            int row = s_row0 + j * 4;
            int node = node0 + row;
            float4 v = make_float4(0.f, 0.f, 0.f, 0.f);
            if (node < n_nodes) v = h4[(size_t)node * 64 + s_f4];
            __half2 p0 = __floats2half2_rn(v.x, v.y);
            __half2 p1 = __floats2half2_rn(v.z, v.w);
            *(uint2*)(smem + SM_A0 + row * APB + s_f4 * 8) =
                make_uint2(*(uint32_t*)&p0, *(uint32_t*)&p1);
        }
    }
    bar_pair(bar_id);

    for (int tile = blockIdx.x; tile < n_tiles; tile += gridDim.x) {
        const int node0 = tile * 128;

        float c[2][8][4];
        #pragma unroll
        for (int mm = 0; mm < 2; mm++)
            #pragma unroll
            for (int nn = 0; nn < 8; nn++)
                #pragma unroll
                for (int q = 0; q < 4; q++) c[mm][nn][q] = 0.f;

        #pragma unroll
        for (int chunk = 0; chunk < 4; chunk++) {
            const int buf = chunk & 1;

            // Prefetch target: next chunk, or next tile's chunk 0 (pair rows).
            int pnode0 = node0, pchunk = chunk + 1;
            bool havepf = true;
            if (chunk == 3) {
                int nt = tile + gridDim.x;
                havepf = nt < n_tiles;
                pnode0 = nt * 128;
                pchunk = 0;
            }
            float4 pf[8];
            if (havepf) {
                #pragma unroll
                for (int j = 0; j < 8; j++) {
                    int node = pnode0 + s_row0 + j * 4;
                    pf[j] = make_float4(0.f, 0.f, 0.f, 0.f);
                    if (node < n_nodes)
                        pf[j] = h4[(size_t)node * 64 + pchunk * 16 + s_f4];
                }
            }

            // MMA over this chunk (4 k16-steps), single term Ah*Bh.
            #pragma unroll
            for (int ks = 0; ks < 4; ks++) {
                const uint32_t akb = (uint32_t)(ks * 32);
                const uint32_t bkb = (uint32_t)(chunk * 128 + ks * 32);

                uint32_t ah[2][4], bh[4][4];
                ldsm4(ah[0], abuf[buf] + akb);
                ldsm4(ah[1], abuf[buf] + 16 * APB + akb);
                #pragma unroll
                for (int p = 0; p < 4; p++)
                    ldsm4(bh[p], baseBH + (uint32_t)(p * 16 * BP * 2) + bkb);

                #pragma unroll
                for (int mm = 0; mm < 2; mm++)
                    #pragma unroll
                    for (int nn = 0; nn < 8; nn++)
                        mma16816(c[mm][nn], ah[mm], bh[nn >> 1][(nn & 1) * 2],
                                 bh[nn >> 1][(nn & 1) * 2 + 1]);
            }

            // Store prefetched rows into the other buffer, pair barrier.
            // (Safe: preceding bar_pair ordered peer's MMAs on that buffer.)
            if (havepf) {
                const int dst = SM_A0 + (1 - buf) * (SM_A1 - SM_A0);
                #pragma unroll
                for (int j = 0; j < 8; j++) {
                    int row = s_row0 + j * 4;
                    __half2 p0 = __floats2half2_rn(pf[j].x, pf[j].y);
                    __half2 p1 = __floats2half2_rn(pf[j].z, pf[j].w);
                    *(uint2*)(smem + dst + row * APB + s_f4 * 8) =
                        make_uint2(*(uint32_t*)&p0, *(uint32_t*)&p1);
                }
                bar_pair(bar_id);
            }
        }

        // Epilogue: fold b1 into cols<64 (warps with wn==0), convert to half2,
        // write g_AB2 rows. Overlaps next-tile chunk-0 ldg latency.
        #pragma unroll
        for (int mm = 0; mm < 2; mm++) {
            #pragma unroll
            for (int nn = 0; nn < 8; nn++) {
                int col = wn * 64 + nn * 8 + tig * 2;
                float bx = 0.f, by = 0.f;
                if (wn == 0) { bx = b1s[col]; by = b1s[col + 1]; }
                int h2i = col >> 1;                 // half2 index within row
                int na = node0 + wm * 32 + mm * 16 + gid;
                if (na < n_nodes)
                    g_AB2[(size_t)na * 64 + h2i] =
                        __floats2half2_rn(c[mm][nn][0] + bx, c[mm][nn][1] + by);
                int nb = na + 8;
                if (nb < n_nodes)
                    g_AB2[(size_t)nb * 64 + h2i] =
                        __floats2half2_rn(c[mm][nn][2] + bx, c[mm][nn][3] + by);
            }
        }
    }
}

// ---------------------------------------------------------------------------
// Kernel 2: per-edge epilogue over fp16 activations. Lane sub=lane&7 owns 8
// hidden channels via ONE uint4 (8 halves) per side; 4 edges per warp-row,
// 2 rows = 8 edges/warp. Per edge-side: 8 lanes x 16 B = one 128 B line.
// out[e] = sum_j relu(A[u][j] + B[v][j]) * W2[j] + b2   (fp32 accumulate)
// ---------------------------------------------------------------------------
__global__ __launch_bounds__(256)
void edge_kernel(const int* __restrict__ ei, const float* __restrict__ W2,
                 const float* __restrict__ b2, float* __restrict__ out, int n_edges)
{
    const int lane = threadIdx.x & 31;
    const int sub  = lane & 7;          // channel group within edge
    const int eg   = lane >> 3;         // 0..3: edge within warp-row
    const int w = (blockIdx.x * blockDim.x + threadIdx.x) >> 5;
    const int e0 = w * 8;
    if (e0 >= n_edges) return;

    const float4 w2a = *(const float4*)&W2[sub * 8];
    const float4 w2b = *(const float4*)&W2[sub * 8 + 4];
    const float bias = b2[0];

    int eidx[2];
    uint4 av[2], bv[2];
    #pragma unroll
    for (int r = 0; r < 2; r++) {
        int e = e0 + r * 4 + eg;
        if (e > n_edges - 1) e = n_edges - 1;   // clamp keeps loads batched
        eidx[r] = e;
        int u = ei[e];
        int v = ei[n_edges + e];
        av[r] = *(const uint4*)&g_AB2[(size_t)u * 64 + sub * 4];
        bv[r] = *(const uint4*)&g_AB2[(size_t)v * 64 + 32 + sub * 4];
    }
    #pragma unroll
    for (int r = 0; r < 2; r++) {
        const __half2* ah = (const __half2*)&av[r];
        const __half2* bh = (const __half2*)&bv[r];
        float2 s0 = __half22float2(__hadd2(ah[0], bh[0]));
        float2 s1 = __half22float2(__hadd2(ah[1], bh[1]));
        float2 s2 = __half22float2(__hadd2(ah[2], bh[2]));
        float2 s3 = __half22float2(__hadd2(ah[3], bh[3]));
        float p;
        p  = fmaxf(s0.x, 0.f) * w2a.x;
        p  = fmaf(fmaxf(s0.y, 0.f), w2a.y, p);
        p  = fmaf(fmaxf(s1.x, 0.f), w2a.z, p);
        p  = fmaf(fmaxf(s1.y, 0.f), w2a.w, p);
        p  = fmaf(fmaxf(s2.x, 0.f), w2b.x, p);
        p  = fmaf(fmaxf(s2.y, 0.f), w2b.y, p);
        p  = fmaf(fmaxf(s3.x, 0.f), w2b.z, p);
        p  = fmaf(fmaxf(s3.y, 0.f), w2b.w, p);
        p += __shfl_xor_sync(0xffffffffu, p, 1);
        p += __shfl_xor_sync(0xffffffffu, p, 2);
        p += __shfl_xor_sync(0xffffffffu, p, 4);
        if (sub == 0 && e0 + r * 4 + eg < n_edges) out[eidx[r]] = p + bias;
    }
}

// ---------------------------------------------------------------------------
// Launch. Inputs (metadata order): h, edge_index (int32), W1, b1, W2, b2.
// ---------------------------------------------------------------------------
extern "C" void kernel_launch(void* const* d_in, const int* in_sizes, int n_in,
                              void* d_out, int out_size)
{
    const float* h   = (const float*)d_in[0];
    const int*   ei  = (const int*)d_in[1];
    const float* W1  = (const float*)d_in[2];
    const float* b1  = (const float*)d_in[3];
    const float* W2  = (const float*)d_in[4];
    const float* b2  = (const float*)d_in[5];
    float*       out = (float*)d_out;

    const int n_nodes = in_sizes[0] / IN_FEATS;   // 100000
    const int n_edges = out_size;                 // 500000
    const int n_tiles = (n_nodes + 127) / 128;    // 782

    cudaFuncSetAttribute(node_gemm_mma,
                         cudaFuncAttributeMaxDynamicSharedMemorySize, SMEM_TOTAL);
    int max_blocks = 2 * NSM;                     // 2 CTAs/SM
    int gemm_blocks = n_tiles < max_blocks ? n_tiles : max_blocks;
    node_gemm_mma<<<gemm_blocks, 256, SMEM_TOTAL>>>((const float4*)h, W1, b1,
                                                    n_nodes, n_tiles);

    int edge_blocks = (n_edges + 63) / 64;        // 64 edges per 256-thread block
    edge_kernel<<<edge_blocks, 256>>>(ei, W2, b2, out, n_edges);
}